// round 2
// baseline (speedup 1.0000x reference)
#include <cuda_runtime.h>

#define SEQ   1024
#define BATCH 32
#define DH    512
#define DIN   512
#define NCTA  128

// ---------------- scratch (device globals; no allocations allowed) ----------
__device__ float g_gates[(size_t)SEQ * BATCH * 4 * DH]; // [t][b][g][h]
__device__ float g_Wt[4 * DH * DH];                     // [g][h][k] transposed recurrent weights
__device__ float g_Ht[2][BATCH * DH];                   // H ping-pong, pair-interleaved transposed:
                                                        //   g_Ht[p][h*32 + (m&15)*2 + (m>>4)] = H[m][h]
__device__ float g_C[BATCH * DH];                       // cell state [m*DH + h]
__device__ unsigned g_bar_count;
__device__ unsigned g_bar_phase;

// ---------------- init ------------------------------------------------------
__global__ void k_init() {
    int i = blockIdx.x * blockDim.x + threadIdx.x;
    if (i == 0) { g_bar_count = 0; g_bar_phase = 0; }
    if (i < BATCH * DH) {
        g_Ht[0][i] = 0.f;
        g_C[i] = 0.f;
    }
}

// ---------------- transpose recurrent weights:  Wt[g][h][k] = Wh_g[k][h] ----
__global__ void k_transpose(const float* __restrict__ W0, const float* __restrict__ W1,
                            const float* __restrict__ W2, const float* __restrict__ W3) {
    __shared__ float tile[32][33];
    int gz = blockIdx.z;
    const float* W = (gz == 0) ? W0 : (gz == 1) ? W1 : (gz == 2) ? W2 : W3;
    int h0 = blockIdx.x * 32;
    int k0 = blockIdx.y * 32;
    for (int r = threadIdx.y; r < 32; r += 8)
        tile[r][threadIdx.x] = W[(size_t)(k0 + r) * DH + h0 + threadIdx.x];
    __syncthreads();
    float* out = g_Wt + (size_t)gz * DH * DH;
    for (int r = threadIdx.y; r < 32; r += 8)
        out[(size_t)(h0 + r) * DH + k0 + threadIdx.x] = tile[threadIdx.x][r];
}

// ---------------- phase 1: input projections (big GEMM) ---------------------
#define BM 128
#define BN 64
#define BK 16
#define APAD 136

__global__ __launch_bounds__(256) void k_xproj(
    const float* __restrict__ x,
    const float* __restrict__ Wi, const float* __restrict__ Wf,
    const float* __restrict__ Wo, const float* __restrict__ Wc,
    const float* __restrict__ bi, const float* __restrict__ bf,
    const float* __restrict__ bo, const float* __restrict__ bc)
{
    __shared__ float As[BK * APAD];
    __shared__ float Bs[BK * BN];

    int tid = threadIdx.x;
    int tx = tid & 15, ty = tid >> 4;
    int m0 = blockIdx.y * BM;
    int n0 = blockIdx.x * BN;
    int g = n0 >> 9;
    int nn0 = n0 & 511;
    const float* W    = (g == 0) ? Wi : (g == 1) ? Wf : (g == 2) ? Wo : Wc;
    const float* bias = (g == 0) ? bi : (g == 1) ? bf : (g == 2) ? bo : bc;

    float c[8][4];
#pragma unroll
    for (int i = 0; i < 8; i++)
#pragma unroll
        for (int j = 0; j < 4; j++) c[i][j] = 0.f;

    for (int k0 = 0; k0 < DIN; k0 += BK) {
#pragma unroll
        for (int u = 0; u < 2; u++) {
            int f = tid + u * 256;
            int m = f >> 2, kq = f & 3;
            float4 v = *(const float4*)(x + (size_t)(m0 + m) * DIN + k0 + kq * 4);
            As[(kq * 4 + 0) * APAD + m] = v.x;
            As[(kq * 4 + 1) * APAD + m] = v.y;
            As[(kq * 4 + 2) * APAD + m] = v.z;
            As[(kq * 4 + 3) * APAD + m] = v.w;
        }
        {
            int k = tid >> 4, nv = tid & 15;
            float4 w = *(const float4*)(W + (size_t)(k0 + k) * DH + nn0 + nv * 4);
            *(float4*)&Bs[k * BN + nv * 4] = w;
        }
        __syncthreads();
#pragma unroll
        for (int k = 0; k < BK; k++) {
            float4 a0 = *(const float4*)&As[k * APAD + ty * 8];
            float4 a1 = *(const float4*)&As[k * APAD + ty * 8 + 4];
            float4 b0 = *(const float4*)&Bs[k * BN + tx * 4];
            float a[8] = {a0.x, a0.y, a0.z, a0.w, a1.x, a1.y, a1.z, a1.w};
            float b[4] = {b0.x, b0.y, b0.z, b0.w};
#pragma unroll
            for (int i = 0; i < 8; i++)
#pragma unroll
                for (int j = 0; j < 4; j++) c[i][j] += a[i] * b[j];
        }
        __syncthreads();
    }
#pragma unroll
    for (int i = 0; i < 8; i++) {
        int r = m0 + ty * 8 + i;
        int b = r >> 10, t = r & 1023;
        float* dst = g_gates + ((size_t)(t * BATCH + b) * 4 + g) * DH + nn0 + tx * 4;
#pragma unroll
        for (int j = 0; j < 4; j++)
            dst[j] = c[i][j] + bias[nn0 + tx * 4 + j];
    }
}

// ---------------- phase 2: persistent recurrence kernel ---------------------
// 128 CTAs (4 h each) x 512 threads: (ml 16) x (hh 4) x (ks 8), all resident.
// Software grid barrier between timesteps (5-node graph; no per-step launches).
#define STEP_THREADS 512

__global__ __launch_bounds__(STEP_THREADS, 1) void k_steps(float* __restrict__ out) {
    __shared__ float red[8 * 4 * 4 * 32];   // [ks][g][hh][m]  16KB

    int tid = threadIdx.x;
    int ml = tid & 15;
    int hh = (tid >> 4) & 3;
    int ks = tid >> 6;
    int h  = blockIdx.x * 4 + hh;

    const float* __restrict__ w0 = g_Wt + 0 * DH * DH + (size_t)h * DH;
    const float* __restrict__ w1 = g_Wt + 1 * DH * DH + (size_t)h * DH;
    const float* __restrict__ w2 = g_Wt + 2 * DH * DH + (size_t)h * DH;
    const float* __restrict__ w3 = g_Wt + 3 * DH * DH + (size_t)h * DH;

    unsigned phase = 0;

    for (int t = 0; t < SEQ; t++) {
        const float2* __restrict__ Hin = (const float2*)g_Ht[t & 1];
        float* __restrict__ Hout = g_Ht[(t + 1) & 1];

        float a00 = 0.f, a01 = 0.f, a10 = 0.f, a11 = 0.f;
        float a20 = 0.f, a21 = 0.f, a30 = 0.f, a31 = 0.f;

        int kb = ks * 64;
#pragma unroll 4
        for (int k = kb; k < kb + 64; k += 4) {
            float4 q0 = *(const float4*)(w0 + k);
            float4 q1 = *(const float4*)(w1 + k);
            float4 q2 = *(const float4*)(w2 + k);
            float4 q3 = *(const float4*)(w3 + k);
            float2 h0 = __ldcg(&Hin[(k + 0) * 16 + ml]);
            float2 h1 = __ldcg(&Hin[(k + 1) * 16 + ml]);
            float2 h2 = __ldcg(&Hin[(k + 2) * 16 + ml]);
            float2 h3 = __ldcg(&Hin[(k + 3) * 16 + ml]);

            a00 += q0.x * h0.x; a01 += q0.x * h0.y;
            a00 += q0.y * h1.x; a01 += q0.y * h1.y;
            a00 += q0.z * h2.x; a01 += q0.z * h2.y;
            a00 += q0.w * h3.x; a01 += q0.w * h3.y;

            a10 += q1.x * h0.x; a11 += q1.x * h0.y;
            a10 += q1.y * h1.x; a11 += q1.y * h1.y;
            a10 += q1.z * h2.x; a11 += q1.z * h2.y;
            a10 += q1.w * h3.x; a11 += q1.w * h3.y;

            a20 += q2.x * h0.x; a21 += q2.x * h0.y;
            a20 += q2.y * h1.x; a21 += q2.y * h1.y;
            a20 += q2.z * h2.x; a21 += q2.z * h2.y;
            a20 += q2.w * h3.x; a21 += q2.w * h3.y;

            a30 += q3.x * h0.x; a31 += q3.x * h0.y;
            a30 += q3.y * h1.x; a31 += q3.y * h1.y;
            a30 += q3.z * h2.x; a31 += q3.z * h2.y;
            a30 += q3.w * h3.x; a31 += q3.w * h3.y;
        }

        red[((ks * 4 + 0) * 4 + hh) * 32 + ml]      = a00;
        red[((ks * 4 + 0) * 4 + hh) * 32 + ml + 16] = a01;
        red[((ks * 4 + 1) * 4 + hh) * 32 + ml]      = a10;
        red[((ks * 4 + 1) * 4 + hh) * 32 + ml + 16] = a11;
        red[((ks * 4 + 2) * 4 + hh) * 32 + ml]      = a20;
        red[((ks * 4 + 2) * 4 + hh) * 32 + ml + 16] = a21;
        red[((ks * 4 + 3) * 4 + hh) * 32 + ml]      = a30;
        red[((ks * 4 + 3) * 4 + hh) * 32 + ml + 16] = a31;
        __syncthreads();

        if (tid < 128) {
            int m = tid & 31;
            int h2 = tid >> 5;
            int hg = blockIdx.x * 4 + h2;

            float s[4];
#pragma unroll
            for (int g = 0; g < 4; g++) {
                float v = 0.f;
#pragma unroll
                for (int kk = 0; kk < 8; kk++)
                    v += red[((kk * 4 + g) * 4 + h2) * 32 + m];
                s[g] = v + g_gates[((size_t)(t * BATCH + m) * 4 + g) * DH + hg];
            }
            float I  = 1.f / (1.f + __expf(-s[0]));
            float F  = 1.f / (1.f + __expf(-s[1]));
            float O  = 1.f / (1.f + __expf(-s[2]));
            float e2 = __expf(2.f * s[3]);
            float Cc = 1.f - 2.f / (e2 + 1.f);     // tanh

            int idx = m * DH + hg;
            float C = F * g_C[idx] + I * Cc;
            g_C[idx] = C;
            float ec = __expf(2.f * C);
            float Hn = O * (1.f - 2.f / (ec + 1.f));

            Hout[hg * 32 + (m & 15) * 2 + (m >> 4)] = Hn;
            out[((size_t)m * SEQ + t) * DH + hg] = Hn;
            __threadfence();   // make H visible before barrier release
        }
        __syncthreads();

        // -------- software grid barrier --------
        if (tid == 0) {
            unsigned arr = atomicAdd(&g_bar_count, 1);
            if (arr == NCTA - 1) {
                g_bar_count = 0;
                __threadfence();
                atomicExch(&g_bar_phase, phase + 1);
            } else {
                while (*(volatile unsigned*)&g_bar_phase <= phase)
                    __nanosleep(32);
                __threadfence();
            }
        }
        __syncthreads();
        phase++;
    }
}

// ---------------- final H copy ---------------------------------------------
__global__ void k_final(float* __restrict__ out) {
    int i = blockIdx.x * blockDim.x + threadIdx.x;
    if (i < BATCH * DH) {
        int m = i >> 9, h = i & 511;
        out[(size_t)BATCH * SEQ * DH + i] = g_Ht[0][h * 32 + (m & 15) * 2 + (m >> 4)];
    }
}

// ---------------- launch ----------------------------------------------------
extern "C" void kernel_launch(void* const* d_in, const int* in_sizes, int n_in,
                              void* d_out, int out_size) {
    const float* x   = (const float*)d_in[0];
    const float* Wxi = (const float*)d_in[1];
    const float* Whi = (const float*)d_in[2];
    const float* bi  = (const float*)d_in[3];
    const float* Wxf = (const float*)d_in[4];
    const float* Whf = (const float*)d_in[5];
    const float* bf  = (const float*)d_in[6];
    const float* Wxo = (const float*)d_in[7];
    const float* Who = (const float*)d_in[8];
    const float* bo  = (const float*)d_in[9];
    const float* Wxc = (const float*)d_in[10];
    const float* Whc = (const float*)d_in[11];
    const float* bc  = (const float*)d_in[12];
    float* out = (float*)d_out;

    k_init<<<64, 256>>>();
    k_transpose<<<dim3(16, 16, 4), dim3(32, 8)>>>(Whi, Whf, Who, Whc);
    k_xproj<<<dim3(2048 / BN, 32768 / BM), 256>>>(x, Wxi, Wxf, Wxo, Wxc, bi, bf, bo, bc);
    k_steps<<<NCTA, STEP_THREADS>>>(out);
    k_final<<<64, 256>>>(out);
}

// round 3
// speedup vs baseline: 1.1297x; 1.1297x over previous
#include <cuda_runtime.h>

#define SEQ   1024
#define BATCH 32
#define DH    512
#define DIN   512
#define NCTA  128

typedef unsigned long long ull;

// ---------------- scratch (device globals; no allocations allowed) ----------
__device__ float g_gates[(size_t)SEQ * BATCH * 4 * DH]; // [t][b][g][h]
__device__ float g_Wt[4 * DH * DH];                     // [g][h][k] transposed recurrent weights
__device__ float g_Ht[2][BATCH * DH];                   // H ping-pong, pair-interleaved transposed:
                                                        //   g_Ht[p][h*32 + (m&15)*2 + (m>>4)] = H[m][h]
__device__ float g_C[BATCH * DH];                       // cell state [m*DH + h]
__device__ unsigned g_bar_count;
__device__ unsigned g_bar_phase;

__device__ __forceinline__ unsigned tf32cvt(float x) {
    unsigned u;
    asm("cvt.rna.tf32.f32 %0, %1;" : "=r"(u) : "f"(x));
    return u;
}

// ---------------- init ------------------------------------------------------
__global__ void k_init() {
    int i = blockIdx.x * blockDim.x + threadIdx.x;
    if (i == 0) { g_bar_count = 0; g_bar_phase = 0; }
    if (i < BATCH * DH) {
        g_Ht[0][i] = 0.f;
        g_C[i] = 0.f;
    }
}

// ---------------- transpose recurrent weights:  Wt[g][h][k] = Wh_g[k][h] ----
__global__ void k_transpose(const float* __restrict__ W0, const float* __restrict__ W1,
                            const float* __restrict__ W2, const float* __restrict__ W3) {
    __shared__ float tile[32][33];
    int gz = blockIdx.z;
    const float* W = (gz == 0) ? W0 : (gz == 1) ? W1 : (gz == 2) ? W2 : W3;
    int h0 = blockIdx.x * 32;
    int k0 = blockIdx.y * 32;
    for (int r = threadIdx.y; r < 32; r += 8)
        tile[r][threadIdx.x] = W[(size_t)(k0 + r) * DH + h0 + threadIdx.x];
    __syncthreads();
    float* out = g_Wt + (size_t)gz * DH * DH;
    for (int r = threadIdx.y; r < 32; r += 8)
        out[(size_t)(h0 + r) * DH + k0 + threadIdx.x] = tile[threadIdx.x][r];
}

// ---------------- phase 1: input projections, tf32 tensor-core GEMM ---------
// C[32768 x 2048] = x[32768 x 512] @ W[512 x 2048(4 gates)] + bias
// CTA tile 128x128, BK=16, 256 thr = 8 warps (4m x 2n), warp tile 32x64.
#define ASTRIDE 20
#define BSTRIDE 136

__global__ __launch_bounds__(256, 1) void k_xproj(
    const float* __restrict__ x,
    const float* __restrict__ Wi, const float* __restrict__ Wf,
    const float* __restrict__ Wo, const float* __restrict__ Wc,
    const float* __restrict__ bi, const float* __restrict__ bf,
    const float* __restrict__ bo, const float* __restrict__ bc)
{
    __shared__ unsigned As[128 * ASTRIDE];   // [m][k] tf32 bits, stride 20 (conflict-free frag reads)
    __shared__ unsigned Bs[16 * BSTRIDE];    // [k][n] tf32 bits, stride 136

    int tid = threadIdx.x;
    int warp = tid >> 5, lane = tid & 31;
    int wm = warp >> 1, wn = warp & 1;
    int grp = lane >> 2, tg = lane & 3;

    int m0 = blockIdx.y * 128;
    int n0 = blockIdx.x * 128;
    int g = n0 >> 9;             // CTA entirely within one gate (512 % 128 == 0)
    int nn0 = n0 & 511;
    const float* W    = (g == 0) ? Wi : (g == 1) ? Wf : (g == 2) ? Wo : Wc;
    const float* bias = (g == 0) ? bi : (g == 1) ? bf : (g == 2) ? bo : bc;

    float c[2][8][4];
#pragma unroll
    for (int i = 0; i < 2; i++)
#pragma unroll
        for (int j = 0; j < 8; j++)
#pragma unroll
            for (int q = 0; q < 4; q++) c[i][j][q] = 0.f;

    // loader coords
    int arow[2], ac4[2], bk[2], bnq[2];
#pragma unroll
    for (int u = 0; u < 2; u++) {
        int ci = tid + u * 256;
        arow[u] = ci >> 2;  ac4[u] = ci & 3;
        bk[u]   = ci >> 5;  bnq[u] = ci & 31;
    }

    float4 pa[2], pb[2];
#pragma unroll
    for (int u = 0; u < 2; u++) {
        pa[u] = *(const float4*)(x + (size_t)(m0 + arow[u]) * DIN + ac4[u] * 4);
        pb[u] = *(const float4*)(W + (size_t)bk[u] * DH + nn0 + bnq[u] * 4);
    }

    for (int kt = 0; kt < DIN; kt += 16) {
        __syncthreads();
#pragma unroll
        for (int u = 0; u < 2; u++) {
            unsigned* pA = &As[arow[u] * ASTRIDE + ac4[u] * 4];
            pA[0] = tf32cvt(pa[u].x); pA[1] = tf32cvt(pa[u].y);
            pA[2] = tf32cvt(pa[u].z); pA[3] = tf32cvt(pa[u].w);
            unsigned* pB = &Bs[bk[u] * BSTRIDE + bnq[u] * 4];
            pB[0] = tf32cvt(pb[u].x); pB[1] = tf32cvt(pb[u].y);
            pB[2] = tf32cvt(pb[u].z); pB[3] = tf32cvt(pb[u].w);
        }
        __syncthreads();
        if (kt + 16 < DIN) {
#pragma unroll
            for (int u = 0; u < 2; u++) {
                pa[u] = *(const float4*)(x + (size_t)(m0 + arow[u]) * DIN + kt + 16 + ac4[u] * 4);
                pb[u] = *(const float4*)(W + (size_t)(kt + 16 + bk[u]) * DH + nn0 + bnq[u] * 4);
            }
        }
#pragma unroll
        for (int kk = 0; kk < 16; kk += 8) {
            unsigned a[2][4], b[8][2];
#pragma unroll
            for (int mf = 0; mf < 2; mf++) {
                int rb = wm * 32 + mf * 16 + grp;
                a[mf][0] = As[rb * ASTRIDE + kk + tg];
                a[mf][1] = As[(rb + 8) * ASTRIDE + kk + tg];
                a[mf][2] = As[rb * ASTRIDE + kk + tg + 4];
                a[mf][3] = As[(rb + 8) * ASTRIDE + kk + tg + 4];
            }
#pragma unroll
            for (int nf = 0; nf < 8; nf++) {
                int cb = wn * 64 + nf * 8 + grp;
                b[nf][0] = Bs[(kk + tg) * BSTRIDE + cb];
                b[nf][1] = Bs[(kk + tg + 4) * BSTRIDE + cb];
            }
#pragma unroll
            for (int mf = 0; mf < 2; mf++)
#pragma unroll
                for (int nf = 0; nf < 8; nf++) {
                    asm volatile(
                        "mma.sync.aligned.m16n8k8.row.col.f32.tf32.tf32.f32 "
                        "{%0,%1,%2,%3}, {%4,%5,%6,%7}, {%8,%9}, {%0,%1,%2,%3};"
                        : "+f"(c[mf][nf][0]), "+f"(c[mf][nf][1]),
                          "+f"(c[mf][nf][2]), "+f"(c[mf][nf][3])
                        : "r"(a[mf][0]), "r"(a[mf][1]), "r"(a[mf][2]), "r"(a[mf][3]),
                          "r"(b[nf][0]), "r"(b[nf][1]));
                }
        }
    }

    // epilogue: bias + scatter to g_gates[t][b][g][h]
#pragma unroll
    for (int mf = 0; mf < 2; mf++) {
        int row0 = m0 + wm * 32 + mf * 16 + grp;
#pragma unroll
        for (int nf = 0; nf < 8; nf++) {
            int h = nn0 + wn * 64 + nf * 8 + tg * 2;
            float2 bb = *(const float2*)(bias + h);
            {
                int b = row0 >> 10, t = row0 & 1023;
                float2 v = make_float2(c[mf][nf][0] + bb.x, c[mf][nf][1] + bb.y);
                *(float2*)(g_gates + ((size_t)(t * BATCH + b) * 4 + g) * DH + h) = v;
            }
            {
                int r1 = row0 + 8;
                int b = r1 >> 10, t = r1 & 1023;
                float2 v = make_float2(c[mf][nf][2] + bb.x, c[mf][nf][3] + bb.y);
                *(float2*)(g_gates + ((size_t)(t * BATCH + b) * 4 + g) * DH + h) = v;
            }
        }
    }
}

// ---------------- phase 2: persistent recurrence, FFMA2 + smem operands ----
// 128 CTAs (4 h each) x 512 threads: (ml 16) x (hh 4) x (ks 8), all resident.
// dynamic smem: Hs 64KB | Ws2 (dup) 64KB | red 16KB | Gs 2KB
#define STEP_THREADS 512
#define SMEM_STEPS (65536 + 65536 + 16384 + 2048)

__global__ __launch_bounds__(STEP_THREADS, 1) void k_steps(float* __restrict__ out) {
    extern __shared__ unsigned char dsm[];
    float2* Hs  = (float2*)dsm;                       // [k*16 + ml] -> (H[ml][k], H[ml+16][k])
    float2* Ws2 = (float2*)(dsm + 65536);             // [(g*4+hh)*512 + k] -> (w, w)
    float*  red = (float*)(dsm + 131072);             // [ks][g][hh][m]
    float*  Gs  = (float*)(dsm + 147456);             // [b*16 + g*4 + h2]

    int tid = threadIdx.x;
    int ml = tid & 15;
    int hh = (tid >> 4) & 3;
    int ks = tid >> 6;
    int bx = blockIdx.x;

    // stage duplicated recurrent weights once (live across all steps)
    for (int j = tid; j < 8192; j += STEP_THREADS) {
        int g = j >> 11, hw = (j >> 9) & 3, k = j & 511;
        float w = g_Wt[(size_t)g * DH * DH + (size_t)(bx * 4 + hw) * DH + k];
        Ws2[j] = make_float2(w, w);
    }

    const ull* w0p = (const ull*)(Ws2 + (0 * 4 + hh) * 512);
    const ull* w1p = (const ull*)(Ws2 + (1 * 4 + hh) * 512);
    const ull* w2p = (const ull*)(Ws2 + (2 * 4 + hh) * 512);
    const ull* w3p = (const ull*)(Ws2 + (3 * 4 + hh) * 512);
    const ull* hsp = (const ull*)Hs;

    unsigned phase = 0;

    for (int t = 0; t < SEQ; t++) {
        // stage H (ping-pong global -> smem), bypass L1 (cross-SM producer)
        {
            const float4* src = (const float4*)g_Ht[t & 1];
            float4* dst = (float4*)Hs;
#pragma unroll
            for (int j = 0; j < 8; j++)
                dst[tid + j * STEP_THREADS] = __ldcg(&src[tid + j * STEP_THREADS]);
        }
        // stage this CTA's gate pre-activations for step t
        Gs[tid] = g_gates[((size_t)(t * BATCH + (tid >> 4)) * 4 + ((tid >> 2) & 3)) * DH
                          + bx * 4 + (tid & 3)];
        __syncthreads();

        ull P0 = 0ull, P1 = 0ull, P2 = 0ull, P3 = 0ull;
        int kb = ks * 64;
#pragma unroll 4
        for (int k = kb; k < kb + 64; k++) {
            ull h2 = hsp[k * 16 + ml];
            ull w0 = w0p[k];
            ull w1 = w1p[k];
            ull w2 = w2p[k];
            ull w3 = w3p[k];
            asm("fma.rn.f32x2 %0, %1, %2, %0;" : "+l"(P0) : "l"(w0), "l"(h2));
            asm("fma.rn.f32x2 %0, %1, %2, %0;" : "+l"(P1) : "l"(w1), "l"(h2));
            asm("fma.rn.f32x2 %0, %1, %2, %0;" : "+l"(P2) : "l"(w2), "l"(h2));
            asm("fma.rn.f32x2 %0, %1, %2, %0;" : "+l"(P3) : "l"(w3), "l"(h2));
        }

        float a00, a01, a10, a11, a20, a21, a30, a31;
        asm("mov.b64 {%0,%1}, %2;" : "=f"(a00), "=f"(a01) : "l"(P0));
        asm("mov.b64 {%0,%1}, %2;" : "=f"(a10), "=f"(a11) : "l"(P1));
        asm("mov.b64 {%0,%1}, %2;" : "=f"(a20), "=f"(a21) : "l"(P2));
        asm("mov.b64 {%0,%1}, %2;" : "=f"(a30), "=f"(a31) : "l"(P3));

        red[((ks * 4 + 0) * 4 + hh) * 32 + ml]      = a00;
        red[((ks * 4 + 0) * 4 + hh) * 32 + ml + 16] = a01;
        red[((ks * 4 + 1) * 4 + hh) * 32 + ml]      = a10;
        red[((ks * 4 + 1) * 4 + hh) * 32 + ml + 16] = a11;
        red[((ks * 4 + 2) * 4 + hh) * 32 + ml]      = a20;
        red[((ks * 4 + 2) * 4 + hh) * 32 + ml + 16] = a21;
        red[((ks * 4 + 3) * 4 + hh) * 32 + ml]      = a30;
        red[((ks * 4 + 3) * 4 + hh) * 32 + ml + 16] = a31;
        __syncthreads();

        if (tid < 128) {
            int m = tid & 31;
            int h2i = tid >> 5;
            int hg = bx * 4 + h2i;

            float s[4];
#pragma unroll
            for (int g = 0; g < 4; g++) {
                float v = 0.f;
#pragma unroll
                for (int kk = 0; kk < 8; kk++)
                    v += red[((kk * 4 + g) * 4 + h2i) * 32 + m];
                s[g] = v + Gs[m * 16 + g * 4 + h2i];
            }
            float I  = 1.f / (1.f + __expf(-s[0]));
            float F  = 1.f / (1.f + __expf(-s[1]));
            float O  = 1.f / (1.f + __expf(-s[2]));
            float e2 = __expf(2.f * s[3]);
            float Cc = 1.f - 2.f / (e2 + 1.f);     // tanh

            int idx = m * DH + hg;
            float C = F * g_C[idx] + I * Cc;
            g_C[idx] = C;
            float ec = __expf(2.f * C);
            float Hn = O * (1.f - 2.f / (ec + 1.f));

            float* Hout = g_Ht[(t + 1) & 1];
            Hout[hg * 32 + (m & 15) * 2 + (m >> 4)] = Hn;
            out[((size_t)m * SEQ + t) * DH + hg] = Hn;
            __threadfence();   // make H visible before barrier release
        }
        __syncthreads();

        // -------- software grid barrier --------
        if (tid == 0) {
            unsigned arr = atomicAdd(&g_bar_count, 1);
            if (arr == NCTA - 1) {
                g_bar_count = 0;
                __threadfence();
                atomicExch(&g_bar_phase, phase + 1);
            } else {
                while (*(volatile unsigned*)&g_bar_phase <= phase)
                    __nanosleep(32);
                __threadfence();
            }
        }
        __syncthreads();
        phase++;
    }
}

// ---------------- final H copy ---------------------------------------------
__global__ void k_final(float* __restrict__ out) {
    int i = blockIdx.x * blockDim.x + threadIdx.x;
    if (i < BATCH * DH) {
        int m = i >> 9, h = i & 511;
        out[(size_t)BATCH * SEQ * DH + i] = g_Ht[0][h * 32 + (m & 15) * 2 + (m >> 4)];
    }
}

// ---------------- launch ----------------------------------------------------
extern "C" void kernel_launch(void* const* d_in, const int* in_sizes, int n_in,
                              void* d_out, int out_size) {
    const float* x   = (const float*)d_in[0];
    const float* Wxi = (const float*)d_in[1];
    const float* Whi = (const float*)d_in[2];
    const float* bi  = (const float*)d_in[3];
    const float* Wxf = (const float*)d_in[4];
    const float* Whf = (const float*)d_in[5];
    const float* bf  = (const float*)d_in[6];
    const float* Wxo = (const float*)d_in[7];
    const float* Who = (const float*)d_in[8];
    const float* bo  = (const float*)d_in[9];
    const float* Wxc = (const float*)d_in[10];
    const float* Whc = (const float*)d_in[11];
    const float* bc  = (const float*)d_in[12];
    float* out = (float*)d_out;

    static int smem_set = 0;
    if (!smem_set) {
        cudaFuncSetAttribute(k_steps, cudaFuncAttributeMaxDynamicSharedMemorySize, SMEM_STEPS);
        smem_set = 1;
    }

    k_init<<<64, 256>>>();
    k_transpose<<<dim3(16, 16, 4), dim3(32, 8)>>>(Whi, Whf, Who, Whc);
    k_xproj<<<dim3(2048 / 128, 32768 / 128), 256>>>(x, Wxi, Wxf, Wxo, Wxc, bi, bf, bo, bc);
    k_steps<<<NCTA, STEP_THREADS, SMEM_STEPS>>>(out);
    k_final<<<64, 256>>>(out);
}

// round 4
// speedup vs baseline: 1.2747x; 1.1284x over previous
#include <cuda_runtime.h>

#define SEQ   1024
#define BATCH 32
#define DH    512
#define DIN   512
#define NCTA  128

typedef unsigned long long ull;

// ---------------- scratch (device globals; no allocations allowed) ----------
__device__ float g_gates[(size_t)SEQ * BATCH * 4 * DH]; // [t][b][g][h]
__device__ float g_Wt[4 * DH * DH];                     // [g][h][k] transposed recurrent weights
__device__ float g_Ht[2][BATCH * DH];                   // H ping-pong, pair-interleaved transposed:
                                                        //   g_Ht[p][h*32 + (m&15)*2 + (m>>4)] = H[m][h]
__device__ float g_C[BATCH * DH];                       // cell state [m*DH + h]
__device__ unsigned g_flags[NCTA * 32];                 // per-CTA step flags, 128B apart

__device__ __forceinline__ unsigned tf32cvt(float x) {
    unsigned u;
    asm("cvt.rna.tf32.f32 %0, %1;" : "=r"(u) : "f"(x));
    return u;
}

// ---------------- init ------------------------------------------------------
__global__ void k_init() {
    int i = blockIdx.x * blockDim.x + threadIdx.x;
    if (i < NCTA * 32) g_flags[i] = 0;
    if (i < BATCH * DH) {
        g_Ht[0][i] = 0.f;
        g_C[i] = 0.f;
    }
}

// ---------------- transpose recurrent weights:  Wt[g][h][k] = Wh_g[k][h] ----
__global__ void k_transpose(const float* __restrict__ W0, const float* __restrict__ W1,
                            const float* __restrict__ W2, const float* __restrict__ W3) {
    __shared__ float tile[32][33];
    int gz = blockIdx.z;
    const float* W = (gz == 0) ? W0 : (gz == 1) ? W1 : (gz == 2) ? W2 : W3;
    int h0 = blockIdx.x * 32;
    int k0 = blockIdx.y * 32;
    for (int r = threadIdx.y; r < 32; r += 8)
        tile[r][threadIdx.x] = W[(size_t)(k0 + r) * DH + h0 + threadIdx.x];
    __syncthreads();
    float* out = g_Wt + (size_t)gz * DH * DH;
    for (int r = threadIdx.y; r < 32; r += 8)
        out[(size_t)(h0 + r) * DH + k0 + threadIdx.x] = tile[threadIdx.x][r];
}

// ---------------- phase 1: input projections, tf32 tensor-core GEMM ---------
#define ASTRIDE 20
#define BSTRIDE 136

__global__ __launch_bounds__(256, 1) void k_xproj(
    const float* __restrict__ x,
    const float* __restrict__ Wi, const float* __restrict__ Wf,
    const float* __restrict__ Wo, const float* __restrict__ Wc,
    const float* __restrict__ bi, const float* __restrict__ bf,
    const float* __restrict__ bo, const float* __restrict__ bc)
{
    __shared__ unsigned As[128 * ASTRIDE];
    __shared__ unsigned Bs[16 * BSTRIDE];

    int tid = threadIdx.x;
    int warp = tid >> 5, lane = tid & 31;
    int wm = warp >> 1, wn = warp & 1;
    int grp = lane >> 2, tg = lane & 3;

    int m0 = blockIdx.y * 128;
    int n0 = blockIdx.x * 128;
    int g = n0 >> 9;
    int nn0 = n0 & 511;
    const float* W    = (g == 0) ? Wi : (g == 1) ? Wf : (g == 2) ? Wo : Wc;
    const float* bias = (g == 0) ? bi : (g == 1) ? bf : (g == 2) ? bo : bc;

    float c[2][8][4];
#pragma unroll
    for (int i = 0; i < 2; i++)
#pragma unroll
        for (int j = 0; j < 8; j++)
#pragma unroll
            for (int q = 0; q < 4; q++) c[i][j][q] = 0.f;

    int arow[2], ac4[2], bk[2], bnq[2];
#pragma unroll
    for (int u = 0; u < 2; u++) {
        int ci = tid + u * 256;
        arow[u] = ci >> 2;  ac4[u] = ci & 3;
        bk[u]   = ci >> 5;  bnq[u] = ci & 31;
    }

    float4 pa[2], pb[2];
#pragma unroll
    for (int u = 0; u < 2; u++) {
        pa[u] = *(const float4*)(x + (size_t)(m0 + arow[u]) * DIN + ac4[u] * 4);
        pb[u] = *(const float4*)(W + (size_t)bk[u] * DH + nn0 + bnq[u] * 4);
    }

    for (int kt = 0; kt < DIN; kt += 16) {
        __syncthreads();
#pragma unroll
        for (int u = 0; u < 2; u++) {
            unsigned* pA = &As[arow[u] * ASTRIDE + ac4[u] * 4];
            pA[0] = tf32cvt(pa[u].x); pA[1] = tf32cvt(pa[u].y);
            pA[2] = tf32cvt(pa[u].z); pA[3] = tf32cvt(pa[u].w);
            unsigned* pB = &Bs[bk[u] * BSTRIDE + bnq[u] * 4];
            pB[0] = tf32cvt(pb[u].x); pB[1] = tf32cvt(pb[u].y);
            pB[2] = tf32cvt(pb[u].z); pB[3] = tf32cvt(pb[u].w);
        }
        __syncthreads();
        if (kt + 16 < DIN) {
#pragma unroll
            for (int u = 0; u < 2; u++) {
                pa[u] = *(const float4*)(x + (size_t)(m0 + arow[u]) * DIN + kt + 16 + ac4[u] * 4);
                pb[u] = *(const float4*)(W + (size_t)(kt + 16 + bk[u]) * DH + nn0 + bnq[u] * 4);
            }
        }
#pragma unroll
        for (int kk = 0; kk < 16; kk += 8) {
            unsigned a[2][4], b[8][2];
#pragma unroll
            for (int mf = 0; mf < 2; mf++) {
                int rb = wm * 32 + mf * 16 + grp;
                a[mf][0] = As[rb * ASTRIDE + kk + tg];
                a[mf][1] = As[(rb + 8) * ASTRIDE + kk + tg];
                a[mf][2] = As[rb * ASTRIDE + kk + tg + 4];
                a[mf][3] = As[(rb + 8) * ASTRIDE + kk + tg + 4];
            }
#pragma unroll
            for (int nf = 0; nf < 8; nf++) {
                int cb = wn * 64 + nf * 8 + grp;
                b[nf][0] = Bs[(kk + tg) * BSTRIDE + cb];
                b[nf][1] = Bs[(kk + tg + 4) * BSTRIDE + cb];
            }
#pragma unroll
            for (int mf = 0; mf < 2; mf++)
#pragma unroll
                for (int nf = 0; nf < 8; nf++) {
                    asm volatile(
                        "mma.sync.aligned.m16n8k8.row.col.f32.tf32.tf32.f32 "
                        "{%0,%1,%2,%3}, {%4,%5,%6,%7}, {%8,%9}, {%0,%1,%2,%3};"
                        : "+f"(c[mf][nf][0]), "+f"(c[mf][nf][1]),
                          "+f"(c[mf][nf][2]), "+f"(c[mf][nf][3])
                        : "r"(a[mf][0]), "r"(a[mf][1]), "r"(a[mf][2]), "r"(a[mf][3]),
                          "r"(b[nf][0]), "r"(b[nf][1]));
                }
        }
    }

#pragma unroll
    for (int mf = 0; mf < 2; mf++) {
        int row0 = m0 + wm * 32 + mf * 16 + grp;
#pragma unroll
        for (int nf = 0; nf < 8; nf++) {
            int h = nn0 + wn * 64 + nf * 8 + tg * 2;
            float2 bb = *(const float2*)(bias + h);
            {
                int b = row0 >> 10, t = row0 & 1023;
                float2 v = make_float2(c[mf][nf][0] + bb.x, c[mf][nf][1] + bb.y);
                *(float2*)(g_gates + ((size_t)(t * BATCH + b) * 4 + g) * DH + h) = v;
            }
            {
                int r1 = row0 + 8;
                int b = r1 >> 10, t = r1 & 1023;
                float2 v = make_float2(c[mf][nf][2] + bb.x, c[mf][nf][3] + bb.y);
                *(float2*)(g_gates + ((size_t)(t * BATCH + b) * 4 + g) * DH + h) = v;
            }
        }
    }
}

// ---------------- phase 2: persistent recurrence, FFMA2 + flag barrier -----
// 128 CTAs (4 h each) x 512 threads: (ml 16) x (hh 4) x (ks 8), all resident.
// dynamic smem: Hs 64KB | Ws2 (dup) 64KB | red 16KB | Gs 2KB
#define STEP_THREADS 512
#define SMEM_STEPS (65536 + 65536 + 16384 + 2048)

__global__ __launch_bounds__(STEP_THREADS, 1) void k_steps(float* __restrict__ out) {
    extern __shared__ unsigned char dsm[];
    float2* Hs  = (float2*)dsm;                       // [k*16 + ml] -> (H[ml][k], H[ml+16][k])
    float2* Ws2 = (float2*)(dsm + 65536);             // [(g*4+hh)*512 + k] -> (w, w)
    float*  red = (float*)(dsm + 131072);             // [ks][g][hh][m]
    float*  Gs  = (float*)(dsm + 147456);             // [b*16 + g*4 + h2]

    int tid = threadIdx.x;
    int ml = tid & 15;
    int hh = (tid >> 4) & 3;
    int ks = tid >> 6;
    int bx = blockIdx.x;

    // stage duplicated recurrent weights once (live across all steps)
    for (int j = tid; j < 8192; j += STEP_THREADS) {
        int g = j >> 11, hw = (j >> 9) & 3, k = j & 511;
        float w = g_Wt[(size_t)g * DH * DH + (size_t)(bx * 4 + hw) * DH + k];
        Ws2[j] = make_float2(w, w);
    }

    const longlong2* w0v = (const longlong2*)(Ws2 + (0 * 4 + hh) * 512);
    const longlong2* w1v = (const longlong2*)(Ws2 + (1 * 4 + hh) * 512);
    const longlong2* w2v = (const longlong2*)(Ws2 + (2 * 4 + hh) * 512);
    const longlong2* w3v = (const longlong2*)(Ws2 + (3 * 4 + hh) * 512);
    const ull* hsp = (const ull*)Hs;

    // gate-staging source index for this thread
    int gs_b = tid >> 4, gs_g = (tid >> 2) & 3, gs_h = tid & 3;
    const float* gsrc = g_gates + ((size_t)gs_b * 4 + gs_g) * DH + bx * 4 + gs_h;

    for (int t = 0; t < SEQ; t++) {
        // ---- stage H (all CTAs' step-t H is visible: flag barrier passed) ----
        {
            const float4* src = (const float4*)g_Ht[t & 1];
            float4* dst = (float4*)Hs;
#pragma unroll
            for (int j = 0; j < 8; j++)
                dst[tid + j * STEP_THREADS] = __ldcg(&src[tid + j * STEP_THREADS]);
        }
        Gs[tid] = __ldg(gsrc + (size_t)t * BATCH * 4 * DH);
        __syncthreads();

        // ---- compute: 4 gates x 2 batch-halves, k in [ks*64, ks*64+64) ----
        ull P0a = 0, P0b = 0, P1a = 0, P1b = 0;
        ull P2a = 0, P2b = 0, P3a = 0, P3b = 0;
        int kb = ks * 64;
#pragma unroll 8
        for (int k = kb; k < kb + 64; k += 2) {
            ull ha = hsp[k * 16 + ml];
            ull hb = hsp[(k + 1) * 16 + ml];
            longlong2 q0 = w0v[k >> 1];
            longlong2 q1 = w1v[k >> 1];
            longlong2 q2 = w2v[k >> 1];
            longlong2 q3 = w3v[k >> 1];
            asm("fma.rn.f32x2 %0, %1, %2, %0;" : "+l"(P0a) : "l"((ull)q0.x), "l"(ha));
            asm("fma.rn.f32x2 %0, %1, %2, %0;" : "+l"(P0b) : "l"((ull)q0.y), "l"(hb));
            asm("fma.rn.f32x2 %0, %1, %2, %0;" : "+l"(P1a) : "l"((ull)q1.x), "l"(ha));
            asm("fma.rn.f32x2 %0, %1, %2, %0;" : "+l"(P1b) : "l"((ull)q1.y), "l"(hb));
            asm("fma.rn.f32x2 %0, %1, %2, %0;" : "+l"(P2a) : "l"((ull)q2.x), "l"(ha));
            asm("fma.rn.f32x2 %0, %1, %2, %0;" : "+l"(P2b) : "l"((ull)q2.y), "l"(hb));
            asm("fma.rn.f32x2 %0, %1, %2, %0;" : "+l"(P3a) : "l"((ull)q3.x), "l"(ha));
            asm("fma.rn.f32x2 %0, %1, %2, %0;" : "+l"(P3b) : "l"((ull)q3.y), "l"(hb));
        }

        float x0, y0, x1, y1;
#define EMIT(Pa, Pb, gidx)                                                      \
        asm("mov.b64 {%0,%1}, %2;" : "=f"(x0), "=f"(y0) : "l"(Pa));             \
        asm("mov.b64 {%0,%1}, %2;" : "=f"(x1), "=f"(y1) : "l"(Pb));             \
        red[((ks * 4 + gidx) * 4 + hh) * 32 + ml]      = x0 + x1;               \
        red[((ks * 4 + gidx) * 4 + hh) * 32 + ml + 16] = y0 + y1;
        EMIT(P0a, P0b, 0)
        EMIT(P1a, P1b, 1)
        EMIT(P2a, P2b, 2)
        EMIT(P3a, P3b, 3)
#undef EMIT
        __syncthreads();

        // ---- epilogue: reduce 8 k-splits, gates, activations ----
        if (tid < 128) {
            int m = tid & 31;
            int h2i = tid >> 5;
            int hg = bx * 4 + h2i;

            float s[4];
#pragma unroll
            for (int g = 0; g < 4; g++) {
                float v = 0.f;
#pragma unroll
                for (int kk = 0; kk < 8; kk++)
                    v += red[((kk * 4 + g) * 4 + h2i) * 32 + m];
                s[g] = v + Gs[m * 16 + g * 4 + h2i];
            }
            float I  = 1.f / (1.f + __expf(-s[0]));
            float F  = 1.f / (1.f + __expf(-s[1]));
            float O  = 1.f / (1.f + __expf(-s[2]));
            float e2 = __expf(2.f * s[3]);
            float Cc = 1.f - 2.f / (e2 + 1.f);     // tanh

            int idx = m * DH + hg;
            float C = F * g_C[idx] + I * Cc;
            g_C[idx] = C;
            float ec = __expf(2.f * C);
            float Hn = O * (1.f - 2.f / (ec + 1.f));

            float* Hout = g_Ht[(t + 1) & 1];
            __stcg(&Hout[hg * 32 + (m & 15) * 2 + (m >> 4)], Hn);
            out[((size_t)m * SEQ + t) * DH + hg] = Hn;
        }
        __syncthreads();

        // ---- flag grid barrier (no contended atomics) ----
        if (tid < 32) {
            if (tid == 0) {
                __threadfence();
                atomicExch(&g_flags[bx * 32], (unsigned)(t + 1));
            }
            unsigned target = (unsigned)(t + 1);
            bool done;
            do {
                done = true;
#pragma unroll
                for (int j = 0; j < 4; j++) {
                    unsigned v = *(volatile unsigned*)&g_flags[(tid * 4 + j) * 32];
                    if (v < target) done = false;
                }
            } while (!__all_sync(0xffffffffu, done));
        }
        __syncthreads();
    }
}

// ---------------- final H copy ---------------------------------------------
__global__ void k_final(float* __restrict__ out) {
    int i = blockIdx.x * blockDim.x + threadIdx.x;
    if (i < BATCH * DH) {
        int m = i >> 9, h = i & 511;
        out[(size_t)BATCH * SEQ * DH + i] = g_Ht[0][h * 32 + (m & 15) * 2 + (m >> 4)];
    }
}

// ---------------- launch ----------------------------------------------------
extern "C" void kernel_launch(void* const* d_in, const int* in_sizes, int n_in,
                              void* d_out, int out_size) {
    const float* x   = (const float*)d_in[0];
    const float* Wxi = (const float*)d_in[1];
    const float* Whi = (const float*)d_in[2];
    const float* bi  = (const float*)d_in[3];
    const float* Wxf = (const float*)d_in[4];
    const float* Whf = (const float*)d_in[5];
    const float* bf  = (const float*)d_in[6];
    const float* Wxo = (const float*)d_in[7];
    const float* Who = (const float*)d_in[8];
    const float* bo  = (const float*)d_in[9];
    const float* Wxc = (const float*)d_in[10];
    const float* Whc = (const float*)d_in[11];
    const float* bc  = (const float*)d_in[12];
    float* out = (float*)d_out;

    static int smem_set = 0;
    if (!smem_set) {
        cudaFuncSetAttribute(k_steps, cudaFuncAttributeMaxDynamicSharedMemorySize, SMEM_STEPS);
        smem_set = 1;
    }

    k_init<<<64, 256>>>();
    k_transpose<<<dim3(16, 16, 4), dim3(32, 8)>>>(Whi, Whf, Who, Whc);
    k_xproj<<<dim3(2048 / 128, 32768 / 128), 256>>>(x, Wxi, Wxf, Wxo, Wxc, bi, bf, bo, bc);
    k_steps<<<NCTA, STEP_THREADS, SMEM_STEPS>>>(out);
    k_final<<<64, 256>>>(out);
}

// round 5
// speedup vs baseline: 1.2896x; 1.0117x over previous
#include <cuda_runtime.h>

#define SEQ   1024
#define BATCH 32
#define DH    512
#define DIN   512
#define NCTA  128

typedef unsigned long long ull;

// ---------------- scratch (device globals; no allocations allowed) ----------
__device__ float g_gates[(size_t)SEQ * BATCH * 4 * DH]; // [t][b][g][h]
__device__ float g_Wt[4 * DH * DH];                     // [g][h][k] transposed recurrent weights
__device__ float g_Ht[2][BATCH * DH];                   // H ping-pong, pair-interleaved transposed:
                                                        //   g_Ht[p][h*32 + (m&15)*2 + (m>>4)] = H[m][h]
__device__ float g_C[BATCH * DH];                       // cell state [m*DH + h]
__device__ unsigned g_flags[NCTA * 32];                 // per-CTA step flags, 128B apart

__device__ __forceinline__ unsigned tf32cvt(float x) {
    unsigned u;
    asm("cvt.rna.tf32.f32 %0, %1;" : "=r"(u) : "f"(x));
    return u;
}

// ---------------- init ------------------------------------------------------
__global__ void k_init() {
    int i = blockIdx.x * blockDim.x + threadIdx.x;
    if (i < NCTA * 32) g_flags[i] = 0;
    if (i < BATCH * DH) {
        g_Ht[0][i] = 0.f;
        g_C[i] = 0.f;
    }
}

// ---------------- transpose recurrent weights:  Wt[g][h][k] = Wh_g[k][h] ----
__global__ void k_transpose(const float* __restrict__ W0, const float* __restrict__ W1,
                            const float* __restrict__ W2, const float* __restrict__ W3) {
    __shared__ float tile[32][33];
    int gz = blockIdx.z;
    const float* W = (gz == 0) ? W0 : (gz == 1) ? W1 : (gz == 2) ? W2 : W3;
    int h0 = blockIdx.x * 32;
    int k0 = blockIdx.y * 32;
    for (int r = threadIdx.y; r < 32; r += 8)
        tile[r][threadIdx.x] = W[(size_t)(k0 + r) * DH + h0 + threadIdx.x];
    __syncthreads();
    float* out = g_Wt + (size_t)gz * DH * DH;
    for (int r = threadIdx.y; r < 32; r += 8)
        out[(size_t)(h0 + r) * DH + k0 + threadIdx.x] = tile[threadIdx.x][r];
}

// ---------------- phase 1: input projections, tf32 tensor-core GEMM ---------
#define ASTRIDE 20
#define BSTRIDE 136

__global__ __launch_bounds__(256, 1) void k_xproj(
    const float* __restrict__ x,
    const float* __restrict__ Wi, const float* __restrict__ Wf,
    const float* __restrict__ Wo, const float* __restrict__ Wc,
    const float* __restrict__ bi, const float* __restrict__ bf,
    const float* __restrict__ bo, const float* __restrict__ bc)
{
    __shared__ unsigned As[128 * ASTRIDE];
    __shared__ unsigned Bs[16 * BSTRIDE];

    int tid = threadIdx.x;
    int warp = tid >> 5, lane = tid & 31;
    int wm = warp >> 1, wn = warp & 1;
    int grp = lane >> 2, tg = lane & 3;

    int m0 = blockIdx.y * 128;
    int n0 = blockIdx.x * 128;
    int g = n0 >> 9;
    int nn0 = n0 & 511;
    const float* W    = (g == 0) ? Wi : (g == 1) ? Wf : (g == 2) ? Wo : Wc;
    const float* bias = (g == 0) ? bi : (g == 1) ? bf : (g == 2) ? bo : bc;

    float c[2][8][4];
#pragma unroll
    for (int i = 0; i < 2; i++)
#pragma unroll
        for (int j = 0; j < 8; j++)
#pragma unroll
            for (int q = 0; q < 4; q++) c[i][j][q] = 0.f;

    int arow[2], ac4[2], bk[2], bnq[2];
#pragma unroll
    for (int u = 0; u < 2; u++) {
        int ci = tid + u * 256;
        arow[u] = ci >> 2;  ac4[u] = ci & 3;
        bk[u]   = ci >> 5;  bnq[u] = ci & 31;
    }

    float4 pa[2], pb[2];
#pragma unroll
    for (int u = 0; u < 2; u++) {
        pa[u] = *(const float4*)(x + (size_t)(m0 + arow[u]) * DIN + ac4[u] * 4);
        pb[u] = *(const float4*)(W + (size_t)bk[u] * DH + nn0 + bnq[u] * 4);
    }

    for (int kt = 0; kt < DIN; kt += 16) {
        __syncthreads();
#pragma unroll
        for (int u = 0; u < 2; u++) {
            unsigned* pA = &As[arow[u] * ASTRIDE + ac4[u] * 4];
            pA[0] = tf32cvt(pa[u].x); pA[1] = tf32cvt(pa[u].y);
            pA[2] = tf32cvt(pa[u].z); pA[3] = tf32cvt(pa[u].w);
            unsigned* pB = &Bs[bk[u] * BSTRIDE + bnq[u] * 4];
            pB[0] = tf32cvt(pb[u].x); pB[1] = tf32cvt(pb[u].y);
            pB[2] = tf32cvt(pb[u].z); pB[3] = tf32cvt(pb[u].w);
        }
        __syncthreads();
        if (kt + 16 < DIN) {
#pragma unroll
            for (int u = 0; u < 2; u++) {
                pa[u] = *(const float4*)(x + (size_t)(m0 + arow[u]) * DIN + kt + 16 + ac4[u] * 4);
                pb[u] = *(const float4*)(W + (size_t)(kt + 16 + bk[u]) * DH + nn0 + bnq[u] * 4);
            }
        }
#pragma unroll
        for (int kk = 0; kk < 16; kk += 8) {
            unsigned a[2][4], b[8][2];
#pragma unroll
            for (int mf = 0; mf < 2; mf++) {
                int rb = wm * 32 + mf * 16 + grp;
                a[mf][0] = As[rb * ASTRIDE + kk + tg];
                a[mf][1] = As[(rb + 8) * ASTRIDE + kk + tg];
                a[mf][2] = As[rb * ASTRIDE + kk + tg + 4];
                a[mf][3] = As[(rb + 8) * ASTRIDE + kk + tg + 4];
            }
#pragma unroll
            for (int nf = 0; nf < 8; nf++) {
                int cb = wn * 64 + nf * 8 + grp;
                b[nf][0] = Bs[(kk + tg) * BSTRIDE + cb];
                b[nf][1] = Bs[(kk + tg + 4) * BSTRIDE + cb];
            }
#pragma unroll
            for (int mf = 0; mf < 2; mf++)
#pragma unroll
                for (int nf = 0; nf < 8; nf++) {
                    asm volatile(
                        "mma.sync.aligned.m16n8k8.row.col.f32.tf32.tf32.f32 "
                        "{%0,%1,%2,%3}, {%4,%5,%6,%7}, {%8,%9}, {%0,%1,%2,%3};"
                        : "+f"(c[mf][nf][0]), "+f"(c[mf][nf][1]),
                          "+f"(c[mf][nf][2]), "+f"(c[mf][nf][3])
                        : "r"(a[mf][0]), "r"(a[mf][1]), "r"(a[mf][2]), "r"(a[mf][3]),
                          "r"(b[nf][0]), "r"(b[nf][1]));
                }
        }
    }

#pragma unroll
    for (int mf = 0; mf < 2; mf++) {
        int row0 = m0 + wm * 32 + mf * 16 + grp;
#pragma unroll
        for (int nf = 0; nf < 8; nf++) {
            int h = nn0 + wn * 64 + nf * 8 + tg * 2;
            float2 bb = *(const float2*)(bias + h);
            {
                int b = row0 >> 10, t = row0 & 1023;
                float2 v = make_float2(c[mf][nf][0] + bb.x, c[mf][nf][1] + bb.y);
                *(float2*)(g_gates + ((size_t)(t * BATCH + b) * 4 + g) * DH + h) = v;
            }
            {
                int r1 = row0 + 8;
                int b = r1 >> 10, t = r1 & 1023;
                float2 v = make_float2(c[mf][nf][2] + bb.x, c[mf][nf][3] + bb.y);
                *(float2*)(g_gates + ((size_t)(t * BATCH + b) * 4 + g) * DH + h) = v;
            }
        }
    }
}

// ---------------- phase 2: persistent recurrence, chunked producer/consumer -
// 128 CTAs (4 h each) x 512 threads: (ml 16) x (hh 4) x (ks 8), all resident.
// Warp group ks reads H rows [64*ks, 64*ks+64), produced by CTAs 16*ks..16*ks+15.
// Each warp waits ONLY on its 16 producers' flags; H read directly from L2.
// dynamic smem: Ws2 (dup) 64KB | red 16KB | Gs 2KB
#define STEP_THREADS 512
#define SMEM_STEPS (65536 + 16384 + 2048)

__global__ __launch_bounds__(STEP_THREADS, 1) void k_steps(float* __restrict__ out) {
    extern __shared__ unsigned char dsm[];
    float2* Ws2 = (float2*)dsm;                       // [(g*4+hh)*512 + k] -> (w, w)
    float*  red = (float*)(dsm + 65536);              // [ks][g][hh][m]
    float*  Gs  = (float*)(dsm + 81920);              // [b*16 + g*4 + h2]

    int tid = threadIdx.x;
    int ml = tid & 15;
    int hh = (tid >> 4) & 3;
    int ks = tid >> 6;
    int lane = tid & 31;
    int bx = blockIdx.x;

    // stage duplicated recurrent weights once (live across all steps)
    for (int j = tid; j < 8192; j += STEP_THREADS) {
        int g = j >> 11, hw = (j >> 9) & 3, k = j & 511;
        float w = g_Wt[(size_t)g * DH * DH + (size_t)(bx * 4 + hw) * DH + k];
        Ws2[j] = make_float2(w, w);
    }
    __syncthreads();

    const longlong2* w0v = (const longlong2*)(Ws2 + (0 * 4 + hh) * 512);
    const longlong2* w1v = (const longlong2*)(Ws2 + (1 * 4 + hh) * 512);
    const longlong2* w2v = (const longlong2*)(Ws2 + (2 * 4 + hh) * 512);
    const longlong2* w3v = (const longlong2*)(Ws2 + (3 * 4 + hh) * 512);

    // this warp's producer flag (one per lane < 16)
    const volatile unsigned* myflag = &g_flags[(ks * 16 + (lane & 15)) * 32];

    int gs_b = tid >> 4, gs_g = (tid >> 2) & 3, gs_h = tid & 3;
    const float* gsrc = g_gates + ((size_t)gs_b * 4 + gs_g) * DH + bx * 4 + gs_h;

    int kb = ks * 64;

    for (int t = 0; t < SEQ; t++) {
        // ---- wait for this chunk's 16 producers (skip t=0: H0 = 0, preset) ----
        if (t > 0) {
            if (lane < 16) {
                unsigned target = (unsigned)t;
                while (*myflag < target) __nanosleep(20);
            }
            __syncwarp();
            __threadfence();
        }

        // stage this CTA's gate pre-activations for step t
        Gs[tid] = __ldg(gsrc + (size_t)t * BATCH * 4 * DH);

        // ---- compute: H chunk read straight from L2, W from smem ----
        const ull* Hg = (const ull*)g_Ht[t & 1];
        ull P0a = 0, P0b = 0, P1a = 0, P1b = 0;
        ull P2a = 0, P2b = 0, P3a = 0, P3b = 0;
#pragma unroll 8
        for (int k = kb; k < kb + 64; k += 2) {
            ull ha, hb;
            asm("ld.global.cg.b64 %0, [%1];" : "=l"(ha) : "l"(Hg + k * 16 + ml));
            asm("ld.global.cg.b64 %0, [%1];" : "=l"(hb) : "l"(Hg + (k + 1) * 16 + ml));
            longlong2 q0 = w0v[k >> 1];
            longlong2 q1 = w1v[k >> 1];
            longlong2 q2 = w2v[k >> 1];
            longlong2 q3 = w3v[k >> 1];
            asm("fma.rn.f32x2 %0, %1, %2, %0;" : "+l"(P0a) : "l"((ull)q0.x), "l"(ha));
            asm("fma.rn.f32x2 %0, %1, %2, %0;" : "+l"(P0b) : "l"((ull)q0.y), "l"(hb));
            asm("fma.rn.f32x2 %0, %1, %2, %0;" : "+l"(P1a) : "l"((ull)q1.x), "l"(ha));
            asm("fma.rn.f32x2 %0, %1, %2, %0;" : "+l"(P1b) : "l"((ull)q1.y), "l"(hb));
            asm("fma.rn.f32x2 %0, %1, %2, %0;" : "+l"(P2a) : "l"((ull)q2.x), "l"(ha));
            asm("fma.rn.f32x2 %0, %1, %2, %0;" : "+l"(P2b) : "l"((ull)q2.y), "l"(hb));
            asm("fma.rn.f32x2 %0, %1, %2, %0;" : "+l"(P3a) : "l"((ull)q3.x), "l"(ha));
            asm("fma.rn.f32x2 %0, %1, %2, %0;" : "+l"(P3b) : "l"((ull)q3.y), "l"(hb));
        }

        float x0, y0, x1, y1;
#define EMIT(Pa, Pb, gidx)                                                      \
        asm("mov.b64 {%0,%1}, %2;" : "=f"(x0), "=f"(y0) : "l"(Pa));             \
        asm("mov.b64 {%0,%1}, %2;" : "=f"(x1), "=f"(y1) : "l"(Pb));             \
        red[((ks * 4 + gidx) * 4 + hh) * 32 + ml]      = x0 + x1;               \
        red[((ks * 4 + gidx) * 4 + hh) * 32 + ml + 16] = y0 + y1;
        EMIT(P0a, P0b, 0)
        EMIT(P1a, P1b, 1)
        EMIT(P2a, P2b, 2)
        EMIT(P3a, P3b, 3)
#undef EMIT
        __syncthreads();

        // ---- epilogue: reduce 8 k-splits, gates, activations ----
        if (tid < 128) {
            int m = tid & 31;
            int h2i = tid >> 5;
            int hg = bx * 4 + h2i;

            float s[4];
#pragma unroll
            for (int g = 0; g < 4; g++) {
                float v = 0.f;
#pragma unroll
                for (int kk = 0; kk < 8; kk++)
                    v += red[((kk * 4 + g) * 4 + h2i) * 32 + m];
                s[g] = v + Gs[m * 16 + g * 4 + h2i];
            }
            float I  = 1.f / (1.f + __expf(-s[0]));
            float F  = 1.f / (1.f + __expf(-s[1]));
            float O  = 1.f / (1.f + __expf(-s[2]));
            float e2 = __expf(2.f * s[3]);
            float Cc = 1.f - 2.f / (e2 + 1.f);     // tanh

            int idx = m * DH + hg;
            float C = F * g_C[idx] + I * Cc;
            g_C[idx] = C;
            float ec = __expf(2.f * C);
            float Hn = O * (1.f - 2.f / (ec + 1.f));

            float* Hout = g_Ht[(t + 1) & 1];
            __stcg(&Hout[hg * 32 + (m & 15) * 2 + (m >> 4)], Hn);
            out[((size_t)m * SEQ + t) * DH + hg] = Hn;
        }
        __syncthreads();

        // ---- publish this CTA's H chunk for step t+1 ----
        if (tid == 0) {
            __threadfence();
            atomicExch(&g_flags[bx * 32], (unsigned)(t + 1));
        }
    }
}

// ---------------- final H copy ---------------------------------------------
__global__ void k_final(float* __restrict__ out) {
    int i = blockIdx.x * blockDim.x + threadIdx.x;
    if (i < BATCH * DH) {
        int m = i >> 9, h = i & 511;
        out[(size_t)BATCH * SEQ * DH + i] = g_Ht[0][h * 32 + (m & 15) * 2 + (m >> 4)];
    }
}

// ---------------- launch ----------------------------------------------------
extern "C" void kernel_launch(void* const* d_in, const int* in_sizes, int n_in,
                              void* d_out, int out_size) {
    const float* x   = (const float*)d_in[0];
    const float* Wxi = (const float*)d_in[1];
    const float* Whi = (const float*)d_in[2];
    const float* bi  = (const float*)d_in[3];
    const float* Wxf = (const float*)d_in[4];
    const float* Whf = (const float*)d_in[5];
    const float* bf  = (const float*)d_in[6];
    const float* Wxo = (const float*)d_in[7];
    const float* Who = (const float*)d_in[8];
    const float* bo  = (const float*)d_in[9];
    const float* Wxc = (const float*)d_in[10];
    const float* Whc = (const float*)d_in[11];
    const float* bc  = (const float*)d_in[12];
    float* out = (float*)d_out;

    static int smem_set = 0;
    if (!smem_set) {
        cudaFuncSetAttribute(k_steps, cudaFuncAttributeMaxDynamicSharedMemorySize, SMEM_STEPS);
        smem_set = 1;
    }

    k_init<<<64, 256>>>();
    k_transpose<<<dim3(16, 16, 4), dim3(32, 8)>>>(Whi, Whf, Who, Whc);
    k_xproj<<<dim3(2048 / 128, 32768 / 128), 256>>>(x, Wxi, Wxf, Wxo, Wxc, bi, bf, bo, bc);
    k_steps<<<NCTA, STEP_THREADS, SMEM_STEPS>>>(out);
    k_final<<<64, 256>>>(out);
}

// round 7
// speedup vs baseline: 1.4806x; 1.1481x over previous
#include <cuda_runtime.h>

#define SEQ   1024
#define BATCH 32
#define DH    512
#define DIN   512
#define NCTA  128

typedef unsigned long long ull;

// ---------------- scratch (device globals; no allocations allowed) ----------
__device__ float g_gates[(size_t)SEQ * BATCH * 4 * DH]; // [t][b][g][h]
__device__ float g_Wt[4 * DH * DH];                     // [g][h][k] transposed recurrent weights
__device__ float g_Ht[2][BATCH * DH];                   // H ping-pong, pair-interleaved transposed:
                                                        //   g_Ht[p][h*32 + (m&15)*2 + (m>>4)] = H[m][h]
__device__ unsigned g_flags[NCTA * 32];                 // per-CTA step flags, 128B apart

__device__ __forceinline__ unsigned tf32cvt(float x) {
    unsigned u;
    asm("cvt.rna.tf32.f32 %0, %1;" : "=r"(u) : "f"(x));
    return u;
}

// ---------------- init ------------------------------------------------------
__global__ void k_init() {
    int i = blockIdx.x * blockDim.x + threadIdx.x;
    if (i < NCTA * 32) g_flags[i] = 0;
    if (i < BATCH * DH) g_Ht[0][i] = 0.f;
}

// ---------------- transpose recurrent weights:  Wt[g][h][k] = Wh_g[k][h] ----
__global__ void k_transpose(const float* __restrict__ W0, const float* __restrict__ W1,
                            const float* __restrict__ W2, const float* __restrict__ W3) {
    __shared__ float tile[32][33];
    int gz = blockIdx.z;
    const float* W = (gz == 0) ? W0 : (gz == 1) ? W1 : (gz == 2) ? W2 : W3;
    int h0 = blockIdx.x * 32;
    int k0 = blockIdx.y * 32;
    for (int r = threadIdx.y; r < 32; r += 8)
        tile[r][threadIdx.x] = W[(size_t)(k0 + r) * DH + h0 + threadIdx.x];
    __syncthreads();
    float* out = g_Wt + (size_t)gz * DH * DH;
    for (int r = threadIdx.y; r < 32; r += 8)
        out[(size_t)(h0 + r) * DH + k0 + threadIdx.x] = tile[threadIdx.x][r];
}

// ---------------- phase 1: input projections, tf32 tensor-core GEMM ---------
#define ASTRIDE 20
#define BSTRIDE 136

__global__ __launch_bounds__(256, 1) void k_xproj(
    const float* __restrict__ x,
    const float* __restrict__ Wi, const float* __restrict__ Wf,
    const float* __restrict__ Wo, const float* __restrict__ Wc,
    const float* __restrict__ bi, const float* __restrict__ bf,
    const float* __restrict__ bo, const float* __restrict__ bc)
{
    __shared__ unsigned As[128 * ASTRIDE];
    __shared__ unsigned Bs[16 * BSTRIDE];

    int tid = threadIdx.x;
    int warp = tid >> 5, lane = tid & 31;
    int wm = warp >> 1, wn = warp & 1;
    int grp = lane >> 2, tg = lane & 3;

    int m0 = blockIdx.y * 128;
    int n0 = blockIdx.x * 128;
    int g = n0 >> 9;
    int nn0 = n0 & 511;
    const float* W    = (g == 0) ? Wi : (g == 1) ? Wf : (g == 2) ? Wo : Wc;
    const float* bias = (g == 0) ? bi : (g == 1) ? bf : (g == 2) ? bo : bc;

    float c[2][8][4];
#pragma unroll
    for (int i = 0; i < 2; i++)
#pragma unroll
        for (int j = 0; j < 8; j++)
#pragma unroll
            for (int q = 0; q < 4; q++) c[i][j][q] = 0.f;

    int arow[2], ac4[2], bk[2], bnq[2];
#pragma unroll
    for (int u = 0; u < 2; u++) {
        int ci = tid + u * 256;
        arow[u] = ci >> 2;  ac4[u] = ci & 3;
        bk[u]   = ci >> 5;  bnq[u] = ci & 31;
    }

    float4 pa[2], pb[2];
#pragma unroll
    for (int u = 0; u < 2; u++) {
        pa[u] = *(const float4*)(x + (size_t)(m0 + arow[u]) * DIN + ac4[u] * 4);
        pb[u] = *(const float4*)(W + (size_t)bk[u] * DH + nn0 + bnq[u] * 4);
    }

    for (int kt = 0; kt < DIN; kt += 16) {
        __syncthreads();
#pragma unroll
        for (int u = 0; u < 2; u++) {
            unsigned* pA = &As[arow[u] * ASTRIDE + ac4[u] * 4];
            pA[0] = tf32cvt(pa[u].x); pA[1] = tf32cvt(pa[u].y);
            pA[2] = tf32cvt(pa[u].z); pA[3] = tf32cvt(pa[u].w);
            unsigned* pB = &Bs[bk[u] * BSTRIDE + bnq[u] * 4];
            pB[0] = tf32cvt(pb[u].x); pB[1] = tf32cvt(pb[u].y);
            pB[2] = tf32cvt(pb[u].z); pB[3] = tf32cvt(pb[u].w);
        }
        __syncthreads();
        if (kt + 16 < DIN) {
#pragma unroll
            for (int u = 0; u < 2; u++) {
                pa[u] = *(const float4*)(x + (size_t)(m0 + arow[u]) * DIN + kt + 16 + ac4[u] * 4);
                pb[u] = *(const float4*)(W + (size_t)(kt + 16 + bk[u]) * DH + nn0 + bnq[u] * 4);
            }
        }
#pragma unroll
        for (int kk = 0; kk < 16; kk += 8) {
            unsigned a[2][4], b[8][2];
#pragma unroll
            for (int mf = 0; mf < 2; mf++) {
                int rb = wm * 32 + mf * 16 + grp;
                a[mf][0] = As[rb * ASTRIDE + kk + tg];
                a[mf][1] = As[(rb + 8) * ASTRIDE + kk + tg];
                a[mf][2] = As[rb * ASTRIDE + kk + tg + 4];
                a[mf][3] = As[(rb + 8) * ASTRIDE + kk + tg + 4];
            }
#pragma unroll
            for (int nf = 0; nf < 8; nf++) {
                int cb = wn * 64 + nf * 8 + grp;
                b[nf][0] = Bs[(kk + tg) * BSTRIDE + cb];
                b[nf][1] = Bs[(kk + tg + 4) * BSTRIDE + cb];
            }
#pragma unroll
            for (int mf = 0; mf < 2; mf++)
#pragma unroll
                for (int nf = 0; nf < 8; nf++) {
                    asm volatile(
                        "mma.sync.aligned.m16n8k8.row.col.f32.tf32.tf32.f32 "
                        "{%0,%1,%2,%3}, {%4,%5,%6,%7}, {%8,%9}, {%0,%1,%2,%3};"
                        : "+f"(c[mf][nf][0]), "+f"(c[mf][nf][1]),
                          "+f"(c[mf][nf][2]), "+f"(c[mf][nf][3])
                        : "r"(a[mf][0]), "r"(a[mf][1]), "r"(a[mf][2]), "r"(a[mf][3]),
                          "r"(b[nf][0]), "r"(b[nf][1]));
                }
        }
    }

#pragma unroll
    for (int mf = 0; mf < 2; mf++) {
        int row0 = m0 + wm * 32 + mf * 16 + grp;
#pragma unroll
        for (int nf = 0; nf < 8; nf++) {
            int h = nn0 + wn * 64 + nf * 8 + tg * 2;
            float2 bb = *(const float2*)(bias + h);
            {
                int b = row0 >> 10, t = row0 & 1023;
                float2 v = make_float2(c[mf][nf][0] + bb.x, c[mf][nf][1] + bb.y);
                *(float2*)(g_gates + ((size_t)(t * BATCH + b) * 4 + g) * DH + h) = v;
            }
            {
                int r1 = row0 + 8;
                int b = r1 >> 10, t = r1 & 1023;
                float2 v = make_float2(c[mf][nf][2] + bb.x, c[mf][nf][3] + bb.y);
                *(float2*)(g_gates + ((size_t)(t * BATCH + b) * 4 + g) * DH + h) = v;
            }
        }
    }
}

// ---------------- phase 2: persistent recurrence ----------------------------
// 128 CTAs (4 h each) x 512 threads: (ml 16) x (hh 4) x (ks 8), all resident.
// Chunked producer flags, HARD SPIN (no nanosleep). C in registers.
// Gates prefetched into a register before the wait; consumed post-compute.
// dynamic smem: Ws2 (dup) 64KB | red 16KB | Gs 2KB
#define STEP_THREADS 512
#define SMEM_STEPS (65536 + 16384 + 2048)

__global__ __launch_bounds__(STEP_THREADS, 1) void k_steps(float* __restrict__ out) {
    extern __shared__ unsigned char dsm[];
    float2* Ws2 = (float2*)dsm;                       // [(g*4+hh)*512 + k] -> (w, w)
    float*  red = (float*)(dsm + 65536);              // [ks][g][hh][m]
    float*  Gs  = (float*)(dsm + 81920);              // [b*16 + g*4 + h2]

    int tid = threadIdx.x;
    int ml = tid & 15;
    int hh = (tid >> 4) & 3;
    int ks = tid >> 6;
    int lane = tid & 31;
    int bx = blockIdx.x;

    // stage duplicated recurrent weights once (live across all steps)
    for (int j = tid; j < 8192; j += STEP_THREADS) {
        int g = j >> 11, hw = (j >> 9) & 3, k = j & 511;
        float w = g_Wt[(size_t)g * DH * DH + (size_t)(bx * 4 + hw) * DH + k];
        Ws2[j] = make_float2(w, w);
    }
    __syncthreads();

    const longlong2* w0v = (const longlong2*)(Ws2 + (0 * 4 + hh) * 512);
    const longlong2* w1v = (const longlong2*)(Ws2 + (1 * 4 + hh) * 512);
    const longlong2* w2v = (const longlong2*)(Ws2 + (2 * 4 + hh) * 512);
    const longlong2* w3v = (const longlong2*)(Ws2 + (3 * 4 + hh) * 512);

    // this warp's producer flag (one per lane < 16)
    const volatile unsigned* myflag = &g_flags[(ks * 16 + (lane & 15)) * 32];

    int gs_b = tid >> 4, gs_g = (tid >> 2) & 3, gs_h = tid & 3;
    const float* gsrc = g_gates + ((size_t)gs_b * 4 + gs_g) * DH + bx * 4 + gs_h;

    // epilogue thread-owned state (tid < 128): cell C lives in a register
    int m_e = tid & 31;
    int h2_e = tid >> 5;
    int hg_e = bx * 4 + h2_e;
    float Creg = 0.f;

    int kb = ks * 64;

    for (int t = 0; t < SEQ; t++) {
        // ---- prefetch gates for this step (DRAM latency overlaps wait+compute)
        float gv = __ldg(gsrc + (size_t)t * BATCH * 4 * DH);

        // ---- wait for this chunk's 16 producers (skip t=0: H0 preset) ----
        if (t > 0) {
            if (lane < 16) {
                unsigned target = (unsigned)t;
                while (*myflag < target) { }      // hard spin, no nanosleep
            }
            __syncwarp();
            __threadfence();
        }

        // ---- compute: H chunk read straight from L2, W from smem ----
        const ull* Hg = (const ull*)g_Ht[t & 1];
        ull P0a = 0, P0b = 0, P1a = 0, P1b = 0;
        ull P2a = 0, P2b = 0, P3a = 0, P3b = 0;
#pragma unroll 8
        for (int k = kb; k < kb + 64; k += 2) {
            ull ha, hb;
            asm("ld.global.cg.b64 %0, [%1];" : "=l"(ha) : "l"(Hg + k * 16 + ml));
            asm("ld.global.cg.b64 %0, [%1];" : "=l"(hb) : "l"(Hg + (k + 1) * 16 + ml));
            longlong2 q0 = w0v[k >> 1];
            longlong2 q1 = w1v[k >> 1];
            longlong2 q2 = w2v[k >> 1];
            longlong2 q3 = w3v[k >> 1];
            asm("fma.rn.f32x2 %0, %1, %2, %0;" : "+l"(P0a) : "l"((ull)q0.x), "l"(ha));
            asm("fma.rn.f32x2 %0, %1, %2, %0;" : "+l"(P0b) : "l"((ull)q0.y), "l"(hb));
            asm("fma.rn.f32x2 %0, %1, %2, %0;" : "+l"(P1a) : "l"((ull)q1.x), "l"(ha));
            asm("fma.rn.f32x2 %0, %1, %2, %0;" : "+l"(P1b) : "l"((ull)q1.y), "l"(hb));
            asm("fma.rn.f32x2 %0, %1, %2, %0;" : "+l"(P2a) : "l"((ull)q2.x), "l"(ha));
            asm("fma.rn.f32x2 %0, %1, %2, %0;" : "+l"(P2b) : "l"((ull)q2.y), "l"(hb));
            asm("fma.rn.f32x2 %0, %1, %2, %0;" : "+l"(P3a) : "l"((ull)q3.x), "l"(ha));
            asm("fma.rn.f32x2 %0, %1, %2, %0;" : "+l"(P3b) : "l"((ull)q3.y), "l"(hb));
        }

        float x0, y0, x1, y1;
#define EMIT(Pa, Pb, gidx)                                                      \
        asm("mov.b64 {%0,%1}, %2;" : "=f"(x0), "=f"(y0) : "l"(Pa));             \
        asm("mov.b64 {%0,%1}, %2;" : "=f"(x1), "=f"(y1) : "l"(Pb));             \
        red[((ks * 4 + gidx) * 4 + hh) * 32 + ml]      = x0 + x1;               \
        red[((ks * 4 + gidx) * 4 + hh) * 32 + ml + 16] = y0 + y1;
        EMIT(P0a, P0b, 0)
        EMIT(P1a, P1b, 1)
        EMIT(P2a, P2b, 2)
        EMIT(P3a, P3b, 3)
#undef EMIT
        Gs[tid] = gv;          // gates now needed; load completed long ago
        __syncthreads();

        // ---- epilogue: reduce 8 k-splits, gates, activations ----
        float Hn = 0.f;
        if (tid < 128) {
            float s[4];
#pragma unroll
            for (int g = 0; g < 4; g++) {
                float v = 0.f;
#pragma unroll
                for (int kk = 0; kk < 8; kk++)
                    v += red[((kk * 4 + g) * 4 + h2_e) * 32 + m_e];
                s[g] = v + Gs[m_e * 16 + g * 4 + h2_e];
            }
            float I  = 1.f / (1.f + __expf(-s[0]));
            float F  = 1.f / (1.f + __expf(-s[1]));
            float O  = 1.f / (1.f + __expf(-s[2]));
            float e2 = __expf(2.f * s[3]);
            float Cc = 1.f - 2.f / (e2 + 1.f);     // tanh

            Creg = F * Creg + I * Cc;
            float ec = __expf(2.f * Creg);
            Hn = O * (1.f - 2.f / (ec + 1.f));

            float* Hout = g_Ht[(t + 1) & 1];
            __stcg(&Hout[hg_e * 32 + (m_e & 15) * 2 + (m_e >> 4)], Hn);
        }
        __syncthreads();

        // ---- publish this CTA's H chunk, then drain the out store ----
        if (tid == 0) {
            __threadfence();
            atomicExch(&g_flags[bx * 32], (unsigned)(t + 1));
        }
        if (tid < 128)
            out[((size_t)m_e * SEQ + t) * DH + hg_e] = Hn;
    }
}

// ---------------- final H copy ---------------------------------------------
__global__ void k_final(float* __restrict__ out) {
    int i = blockIdx.x * blockDim.x + threadIdx.x;
    if (i < BATCH * DH) {
        int m = i >> 9, h = i & 511;
        out[(size_t)BATCH * SEQ * DH + i] = g_Ht[0][h * 32 + (m & 15) * 2 + (m >> 4)];
    }
}

// ---------------- launch ----------------------------------------------------
extern "C" void kernel_launch(void* const* d_in, const int* in_sizes, int n_in,
                              void* d_out, int out_size) {
    const float* x   = (const float*)d_in[0];
    const float* Wxi = (const float*)d_in[1];
    const float* Whi = (const float*)d_in[2];
    const float* bi  = (const float*)d_in[3];
    const float* Wxf = (const float*)d_in[4];
    const float* Whf = (const float*)d_in[5];
    const float* bf  = (const float*)d_in[6];
    const float* Wxo = (const float*)d_in[7];
    const float* Who = (const float*)d_in[8];
    const float* bo  = (const float*)d_in[9];
    const float* Wxc = (const float*)d_in[10];
    const float* Whc = (const float*)d_in[11];
    const float* bc  = (const float*)d_in[12];
    float* out = (float*)d_out;

    static int smem_set = 0;
    if (!smem_set) {
        cudaFuncSetAttribute(k_steps, cudaFuncAttributeMaxDynamicSharedMemorySize, SMEM_STEPS);
        smem_set = 1;
    }

    k_init<<<64, 256>>>();
    k_transpose<<<dim3(16, 16, 4), dim3(32, 8)>>>(Whi, Whf, Who, Whc);
    k_xproj<<<dim3(2048 / 128, 32768 / 128), 256>>>(x, Wxi, Wxf, Wxo, Wxc, bi, bf, bo, bc);
    k_steps<<<NCTA, STEP_THREADS, SMEM_STEPS>>>(out);
    k_final<<<64, 256>>>(out);
}

// round 8
// speedup vs baseline: 2.1650x; 1.4622x over previous
#include <cuda_runtime.h>

#define SEQ   1024
#define BATCH 32
#define DH    512
#define DIN   512
#define NCTA  128

typedef unsigned long long ull;

// ---------------- scratch (device globals; no allocations allowed) ----------
__device__ float g_gates[(size_t)SEQ * BATCH * 4 * DH]; // [t][b][g][h]
__device__ float g_Wt[4 * DH * DH];                     // [g][h][k] transposed recurrent weights
__device__ float g_H[2][BATCH * DH];                    // H ping-pong in A-fragment layout:
                                                        //  idx = ((K8*2+mt)*32 + grp*4+tg)*4 + khigh*2+mhigh
__device__ unsigned g_flags[NCTA * 32];                 // per-CTA step flags, 128B apart

__device__ __forceinline__ unsigned tf32cvt(float x) {
    unsigned u;
    asm("cvt.rna.tf32.f32 %0, %1;" : "=r"(u) : "f"(x));
    return u;
}

// ---------------- init ------------------------------------------------------
__global__ void k_init() {
    int i = blockIdx.x * blockDim.x + threadIdx.x;
    if (i < NCTA * 32) g_flags[i] = 0;
    if (i < 2 * BATCH * DH) ((float*)g_H)[i] = 0.f;
}

// ---------------- transpose recurrent weights:  Wt[g][h][k] = Wh_g[k][h] ----
__global__ void k_transpose(const float* __restrict__ W0, const float* __restrict__ W1,
                            const float* __restrict__ W2, const float* __restrict__ W3) {
    __shared__ float tile[32][33];
    int gz = blockIdx.z;
    const float* W = (gz == 0) ? W0 : (gz == 1) ? W1 : (gz == 2) ? W2 : W3;
    int h0 = blockIdx.x * 32;
    int k0 = blockIdx.y * 32;
    for (int r = threadIdx.y; r < 32; r += 8)
        tile[r][threadIdx.x] = W[(size_t)(k0 + r) * DH + h0 + threadIdx.x];
    __syncthreads();
    float* out = g_Wt + (size_t)gz * DH * DH;
    for (int r = threadIdx.y; r < 32; r += 8)
        out[(size_t)(h0 + r) * DH + k0 + threadIdx.x] = tile[threadIdx.x][r];
}

// ---------------- phase 1: input projections, tf32 tensor-core GEMM ---------
#define ASTRIDE 20
#define BSTRIDE 136

__global__ __launch_bounds__(256, 1) void k_xproj(
    const float* __restrict__ x,
    const float* __restrict__ Wi, const float* __restrict__ Wf,
    const float* __restrict__ Wo, const float* __restrict__ Wc,
    const float* __restrict__ bi, const float* __restrict__ bf,
    const float* __restrict__ bo, const float* __restrict__ bc)
{
    __shared__ unsigned As[128 * ASTRIDE];
    __shared__ unsigned Bs[16 * BSTRIDE];

    int tid = threadIdx.x;
    int warp = tid >> 5, lane = tid & 31;
    int wm = warp >> 1, wn = warp & 1;
    int grp = lane >> 2, tg = lane & 3;

    int m0 = blockIdx.y * 128;
    int n0 = blockIdx.x * 128;
    int g = n0 >> 9;
    int nn0 = n0 & 511;
    const float* W    = (g == 0) ? Wi : (g == 1) ? Wf : (g == 2) ? Wo : Wc;
    const float* bias = (g == 0) ? bi : (g == 1) ? bf : (g == 2) ? bo : bc;

    float c[2][8][4];
#pragma unroll
    for (int i = 0; i < 2; i++)
#pragma unroll
        for (int j = 0; j < 8; j++)
#pragma unroll
            for (int q = 0; q < 4; q++) c[i][j][q] = 0.f;

    int arow[2], ac4[2], bk[2], bnq[2];
#pragma unroll
    for (int u = 0; u < 2; u++) {
        int ci = tid + u * 256;
        arow[u] = ci >> 2;  ac4[u] = ci & 3;
        bk[u]   = ci >> 5;  bnq[u] = ci & 31;
    }

    float4 pa[2], pb[2];
#pragma unroll
    for (int u = 0; u < 2; u++) {
        pa[u] = *(const float4*)(x + (size_t)(m0 + arow[u]) * DIN + ac4[u] * 4);
        pb[u] = *(const float4*)(W + (size_t)bk[u] * DH + nn0 + bnq[u] * 4);
    }

    for (int kt = 0; kt < DIN; kt += 16) {
        __syncthreads();
#pragma unroll
        for (int u = 0; u < 2; u++) {
            unsigned* pA = &As[arow[u] * ASTRIDE + ac4[u] * 4];
            pA[0] = tf32cvt(pa[u].x); pA[1] = tf32cvt(pa[u].y);
            pA[2] = tf32cvt(pa[u].z); pA[3] = tf32cvt(pa[u].w);
            unsigned* pB = &Bs[bk[u] * BSTRIDE + bnq[u] * 4];
            pB[0] = tf32cvt(pb[u].x); pB[1] = tf32cvt(pb[u].y);
            pB[2] = tf32cvt(pb[u].z); pB[3] = tf32cvt(pb[u].w);
        }
        __syncthreads();
        if (kt + 16 < DIN) {
#pragma unroll
            for (int u = 0; u < 2; u++) {
                pa[u] = *(const float4*)(x + (size_t)(m0 + arow[u]) * DIN + kt + 16 + ac4[u] * 4);
                pb[u] = *(const float4*)(W + (size_t)(kt + 16 + bk[u]) * DH + nn0 + bnq[u] * 4);
            }
        }
#pragma unroll
        for (int kk = 0; kk < 16; kk += 8) {
            unsigned a[2][4], b[8][2];
#pragma unroll
            for (int mf = 0; mf < 2; mf++) {
                int rb = wm * 32 + mf * 16 + grp;
                a[mf][0] = As[rb * ASTRIDE + kk + tg];
                a[mf][1] = As[(rb + 8) * ASTRIDE + kk + tg];
                a[mf][2] = As[rb * ASTRIDE + kk + tg + 4];
                a[mf][3] = As[(rb + 8) * ASTRIDE + kk + tg + 4];
            }
#pragma unroll
            for (int nf = 0; nf < 8; nf++) {
                int cb = wn * 64 + nf * 8 + grp;
                b[nf][0] = Bs[(kk + tg) * BSTRIDE + cb];
                b[nf][1] = Bs[(kk + tg + 4) * BSTRIDE + cb];
            }
#pragma unroll
            for (int mf = 0; mf < 2; mf++)
#pragma unroll
                for (int nf = 0; nf < 8; nf++) {
                    asm volatile(
                        "mma.sync.aligned.m16n8k8.row.col.f32.tf32.tf32.f32 "
                        "{%0,%1,%2,%3}, {%4,%5,%6,%7}, {%8,%9}, {%0,%1,%2,%3};"
                        : "+f"(c[mf][nf][0]), "+f"(c[mf][nf][1]),
                          "+f"(c[mf][nf][2]), "+f"(c[mf][nf][3])
                        : "r"(a[mf][0]), "r"(a[mf][1]), "r"(a[mf][2]), "r"(a[mf][3]),
                          "r"(b[nf][0]), "r"(b[nf][1]));
                }
        }
    }

#pragma unroll
    for (int mf = 0; mf < 2; mf++) {
        int row0 = m0 + wm * 32 + mf * 16 + grp;
#pragma unroll
        for (int nf = 0; nf < 8; nf++) {
            int h = nn0 + wn * 64 + nf * 8 + tg * 2;
            float2 bb = *(const float2*)(bias + h);
            {
                int b = row0 >> 10, t = row0 & 1023;
                float2 v = make_float2(c[mf][nf][0] + bb.x, c[mf][nf][1] + bb.y);
                *(float2*)(g_gates + ((size_t)(t * BATCH + b) * 4 + g) * DH + h) = v;
            }
            {
                int r1 = row0 + 8;
                int b = r1 >> 10, t = r1 & 1023;
                float2 v = make_float2(c[mf][nf][2] + bb.x, c[mf][nf][3] + bb.y);
                *(float2*)(g_gates + ((size_t)(t * BATCH + b) * 4 + g) * DH + h) = v;
            }
        }
    }
}

// ---------------- phase 2: persistent recurrence, tensor-core ---------------
// 128 CTAs x 512 threads (16 warps). CTA bx owns outputs n = g*4+h2 (16 cols),
// h = bx*4+h2. Warp ws covers K in [32*ws, 32*ws+32). Split-tf32 (3 mma).
// W fragments live in registers for all 1024 steps. red: [ws][m][n] stride 24.
#define STEP_THREADS 512
#define RS 24
#define SMEM_STEPS (16 * 32 * RS * 4)

#define MMA_T(C, A, B)                                                          \
    asm volatile(                                                               \
        "mma.sync.aligned.m16n8k8.row.col.f32.tf32.tf32.f32 "                   \
        "{%0,%1,%2,%3}, {%4,%5,%6,%7}, {%8,%9}, {%0,%1,%2,%3};"                 \
        : "+f"(C[0]), "+f"(C[1]), "+f"(C[2]), "+f"(C[3])                        \
        : "r"(A[0]), "r"(A[1]), "r"(A[2]), "r"(A[3]), "r"(B[0]), "r"(B[1]));

__global__ __launch_bounds__(STEP_THREADS, 1) void k_steps(float* __restrict__ out) {
    extern __shared__ float red[];   // [ws][m(32)][RS], n in [0,16)

    int tid = threadIdx.x;
    int lane = tid & 31;
    int ws = tid >> 5;
    int grp = lane >> 2, tg = lane & 3;
    int bx = blockIdx.x;

    // ---- precompute W fragments (big + small), resident all steps ----------
    unsigned wb[2][4][2], wsm[2][4][2];
#pragma unroll
    for (int nt = 0; nt < 2; nt++) {
        int n = nt * 8 + grp;
        int g = n >> 2, h2 = n & 3;
        const float* wrow = g_Wt + (size_t)g * DH * DH + (size_t)(bx * 4 + h2) * DH;
#pragma unroll
        for (int q = 0; q < 4; q++) {
            int k0 = 32 * ws + 8 * q + tg;
#pragma unroll
            for (int u = 0; u < 2; u++) {
                float w = wrow[k0 + u * 4];
                unsigned b = tf32cvt(w);
                wb[nt][q][u] = b;
                wsm[nt][q][u] = tf32cvt(w - __uint_as_float(b));
            }
        }
    }

    // this warp's producer flags: CTAs 8*ws .. 8*ws+7 (lanes 0..7 poll)
    const volatile unsigned* myflag = &g_flags[(ws * 8 + (lane & 7)) * 32];

    // per-thread reduction/epilogue identity: (m, n)
    int m_r = tid >> 4;
    int n_r = tid & 15;
    const float* gsrc = g_gates + ((size_t)m_r * 4 + (n_r >> 2)) * DH + bx * 4 + (n_r & 3);

    // leader (n_r < 4) H-write index in fragment layout
    int hg_e = bx * 4 + n_r;                 // n_r = h2 for leaders
    int mtE = m_r >> 4, mmE = m_r & 15;
    int grpE = mmE & 7, mhighE = mmE >> 3;
    int K8E = hg_e >> 3, kkE = hg_e & 7;
    int tgE = kkE & 3, khighE = kkE >> 2;
    int idxE = (((K8E * 2 + mtE) * 32) + grpE * 4 + tgE) * 4 + (khighE * 2 + mhighE);
    float Creg = 0.f;

    for (int t = 0; t < SEQ; t++) {
        // ---- prefetch this thread's gate pre-activation (DRAM, overlaps wait)
        float gv = __ldg(gsrc + (size_t)t * BATCH * 4 * DH);

        // ---- wait for this warp's 8 producers (skip t=0: H0 preset to 0) ----
        if (t > 0) {
            if (lane < 8) {
                unsigned target = (unsigned)t;
                while (*myflag < target) { }
            }
            __syncwarp();
            __threadfence();
        }

        // ---- tensor-core compute: C[2][2][4] over K=32 ----
        const float* Hb = g_H[t & 1];
        float c[2][2][4];
#pragma unroll
        for (int i = 0; i < 2; i++)
#pragma unroll
            for (int j = 0; j < 2; j++)
#pragma unroll
                for (int q = 0; q < 4; q++) c[i][j][q] = 0.f;

#pragma unroll
        for (int q = 0; q < 4; q++) {
            int K8 = ws * 4 + q;
#pragma unroll
            for (int mt = 0; mt < 2; mt++) {
                float4 av;
                asm("ld.global.cg.v4.f32 {%0,%1,%2,%3}, [%4];"
                    : "=f"(av.x), "=f"(av.y), "=f"(av.z), "=f"(av.w)
                    : "l"(Hb + ((size_t)(K8 * 2 + mt) * 32 + lane) * 4));
                unsigned ab[4], as_[4];
                ab[0] = tf32cvt(av.x); as_[0] = tf32cvt(av.x - __uint_as_float(ab[0]));
                ab[1] = tf32cvt(av.y); as_[1] = tf32cvt(av.y - __uint_as_float(ab[1]));
                ab[2] = tf32cvt(av.z); as_[2] = tf32cvt(av.z - __uint_as_float(ab[2]));
                ab[3] = tf32cvt(av.w); as_[3] = tf32cvt(av.w - __uint_as_float(ab[3]));
#pragma unroll
                for (int nt = 0; nt < 2; nt++) {
                    MMA_T(c[mt][nt], ab,  wb[nt][q]);
                    MMA_T(c[mt][nt], ab,  wsm[nt][q]);
                    MMA_T(c[mt][nt], as_, wb[nt][q]);
                }
            }
        }

        // ---- store partials to red[ws][m][n] ----
#pragma unroll
        for (int mt = 0; mt < 2; mt++)
#pragma unroll
            for (int nt = 0; nt < 2; nt++) {
                float* r0 = &red[((ws * 32) + 16 * mt + grp) * RS + nt * 8 + 2 * tg];
                *(float2*)r0            = make_float2(c[mt][nt][0], c[mt][nt][1]);
                *(float2*)(r0 + 8 * RS) = make_float2(c[mt][nt][2], c[mt][nt][3]);
            }
        __syncthreads();

        // ---- 16-way k-split reduction (all 512 threads, one (m,n) each) ----
        float s0 = gv, s1 = 0.f, s2 = 0.f, s3 = 0.f;
        {
            const float* rp = &red[m_r * RS + n_r];
#pragma unroll
            for (int w4 = 0; w4 < 4; w4++) {
                s0 += rp[(w4 * 4 + 0) * 32 * RS];
                s1 += rp[(w4 * 4 + 1) * 32 * RS];
                s2 += rp[(w4 * 4 + 2) * 32 * RS];
                s3 += rp[(w4 * 4 + 3) * 32 * RS];
            }
        }
        float s = (s0 + s1) + (s2 + s3);

        // gather the 4 gate sums to leaders (n_r < 4) via shfl
        float v1 = __shfl_sync(0xffffffffu, s, lane + 4);
        float v2 = __shfl_sync(0xffffffffu, s, lane + 8);
        float v3 = __shfl_sync(0xffffffffu, s, lane + 12);

        float Hn = 0.f;
        if (n_r < 4) {
            float I  = 1.f / (1.f + __expf(-s));
            float F  = 1.f / (1.f + __expf(-v1));
            float O  = 1.f / (1.f + __expf(-v2));
            float e2 = __expf(2.f * v3);
            float Cc = 1.f - 2.f / (e2 + 1.f);     // tanh

            Creg = F * Creg + I * Cc;
            float ec = __expf(2.f * Creg);
            Hn = O * (1.f - 2.f / (ec + 1.f));

            __stcg(&g_H[(t + 1) & 1][idxE], Hn);
        }
        __syncthreads();

        // ---- publish (cooperative-groups pattern: bar, then 1 fence+flag) ----
        if (tid == 0) {
            __threadfence();
            atomicExch(&g_flags[bx * 32], (unsigned)(t + 1));
        }
        if (n_r < 4)
            out[((size_t)m_r * SEQ + t) * DH + hg_e] = Hn;
    }
}

// ---------------- final H copy ---------------------------------------------
__global__ void k_final(float* __restrict__ out) {
    int i = blockIdx.x * blockDim.x + threadIdx.x;
    if (i < BATCH * DH) {
        int m = i >> 9, h = i & 511;
        int mt = m >> 4, mm = m & 15;
        int grp = mm & 7, mhigh = mm >> 3;
        int K8 = h >> 3, kk = h & 7;
        int tg = kk & 3, khigh = kk >> 2;
        int idx = (((K8 * 2 + mt) * 32) + grp * 4 + tg) * 4 + (khigh * 2 + mhigh);
        out[(size_t)BATCH * SEQ * DH + i] = g_H[0][idx];
    }
}

// ---------------- launch ----------------------------------------------------
extern "C" void kernel_launch(void* const* d_in, const int* in_sizes, int n_in,
                              void* d_out, int out_size) {
    const float* x   = (const float*)d_in[0];
    const float* Wxi = (const float*)d_in[1];
    const float* Whi = (const float*)d_in[2];
    const float* bi  = (const float*)d_in[3];
    const float* Wxf = (const float*)d_in[4];
    const float* Whf = (const float*)d_in[5];
    const float* bf  = (const float*)d_in[6];
    const float* Wxo = (const float*)d_in[7];
    const float* Who = (const float*)d_in[8];
    const float* bo  = (const float*)d_in[9];
    const float* Wxc = (const float*)d_in[10];
    const float* Whc = (const float*)d_in[11];
    const float* bc  = (const float*)d_in[12];
    float* out = (float*)d_out;

    static int smem_set = 0;
    if (!smem_set) {
        cudaFuncSetAttribute(k_steps, cudaFuncAttributeMaxDynamicSharedMemorySize, SMEM_STEPS);
        smem_set = 1;
    }

    k_init<<<128, 256>>>();
    k_transpose<<<dim3(16, 16, 4), dim3(32, 8)>>>(Whi, Whf, Who, Whc);
    k_xproj<<<dim3(2048 / 128, 32768 / 128), 256>>>(x, Wxi, Wxf, Wxo, Wxc, bi, bf, bo, bc);
    k_steps<<<NCTA, STEP_THREADS, SMEM_STEPS>>>(out);
    k_final<<<64, 256>>>(out);
}

// round 11
// speedup vs baseline: 2.4491x; 1.1312x over previous
#include <cuda_runtime.h>

#define SEQ   1024
#define BATCH 32
#define DH    512
#define DIN   512
#define NCTA  128

typedef unsigned long long ull;

// ---------------- scratch (device globals; no allocations allowed) ----------
__device__ float g_gates[(size_t)SEQ * BATCH * 4 * DH]; // [t][b][g][h]
__device__ float g_Wt[4 * DH * DH];                     // [g][h][k] transposed recurrent weights
__device__ float g_H[2][2][BATCH * DH];                 // [pingpong][big/small] in A-fragment layout:
                                                        //  idx = ((K8*2+mt)*32 + grp*4+tg)*4 + khigh*2+mhigh
__device__ unsigned g_flags[NCTA * 32];                 // per-CTA step flags, 128B apart

__device__ __forceinline__ unsigned tf32cvt(float x) {
    unsigned u;
    asm("cvt.rna.tf32.f32 %0, %1;" : "=r"(u) : "f"(x));
    return u;
}

// ---------------- init ------------------------------------------------------
__global__ void k_init() {
    int i = blockIdx.x * blockDim.x + threadIdx.x;
    if (i < NCTA * 32) g_flags[i] = 0;
    if (i < 2 * 2 * BATCH * DH) ((float*)g_H)[i] = 0.f;
}

// ---------------- transpose recurrent weights:  Wt[g][h][k] = Wh_g[k][h] ----
__global__ void k_transpose(const float* __restrict__ W0, const float* __restrict__ W1,
                            const float* __restrict__ W2, const float* __restrict__ W3) {
    __shared__ float tile[32][33];
    int gz = blockIdx.z;
    const float* W = (gz == 0) ? W0 : (gz == 1) ? W1 : (gz == 2) ? W2 : W3;
    int h0 = blockIdx.x * 32;
    int k0 = blockIdx.y * 32;
    for (int r = threadIdx.y; r < 32; r += 8)
        tile[r][threadIdx.x] = W[(size_t)(k0 + r) * DH + h0 + threadIdx.x];
    __syncthreads();
    float* out = g_Wt + (size_t)gz * DH * DH;
    for (int r = threadIdx.y; r < 32; r += 8)
        out[(size_t)(h0 + r) * DH + k0 + threadIdx.x] = tile[threadIdx.x][r];
}

// ---------------- phase 1: input projections, tf32 tensor-core GEMM ---------
#define ASTRIDE 20
#define BSTRIDE 136

__global__ __launch_bounds__(256, 1) void k_xproj(
    const float* __restrict__ x,
    const float* __restrict__ Wi, const float* __restrict__ Wf,
    const float* __restrict__ Wo, const float* __restrict__ Wc,
    const float* __restrict__ bi, const float* __restrict__ bf,
    const float* __restrict__ bo, const float* __restrict__ bc)
{
    __shared__ unsigned As[128 * ASTRIDE];
    __shared__ unsigned Bs[16 * BSTRIDE];

    int tid = threadIdx.x;
    int warp = tid >> 5, lane = tid & 31;
    int wm = warp >> 1, wn = warp & 1;
    int grp = lane >> 2, tg = lane & 3;

    int m0 = blockIdx.y * 128;
    int n0 = blockIdx.x * 128;
    int g = n0 >> 9;
    int nn0 = n0 & 511;
    const float* W    = (g == 0) ? Wi : (g == 1) ? Wf : (g == 2) ? Wo : Wc;
    const float* bias = (g == 0) ? bi : (g == 1) ? bf : (g == 2) ? bo : bc;

    float c[2][8][4];
#pragma unroll
    for (int i = 0; i < 2; i++)
#pragma unroll
        for (int j = 0; j < 8; j++)
#pragma unroll
            for (int q = 0; q < 4; q++) c[i][j][q] = 0.f;

    int arow[2], ac4[2], bk[2], bnq[2];
#pragma unroll
    for (int u = 0; u < 2; u++) {
        int ci = tid + u * 256;
        arow[u] = ci >> 2;  ac4[u] = ci & 3;
        bk[u]   = ci >> 5;  bnq[u] = ci & 31;
    }

    float4 pa[2], pb[2];
#pragma unroll
    for (int u = 0; u < 2; u++) {
        pa[u] = *(const float4*)(x + (size_t)(m0 + arow[u]) * DIN + ac4[u] * 4);
        pb[u] = *(const float4*)(W + (size_t)bk[u] * DH + nn0 + bnq[u] * 4);
    }

    for (int kt = 0; kt < DIN; kt += 16) {
        __syncthreads();
#pragma unroll
        for (int u = 0; u < 2; u++) {
            unsigned* pA = &As[arow[u] * ASTRIDE + ac4[u] * 4];
            pA[0] = tf32cvt(pa[u].x); pA[1] = tf32cvt(pa[u].y);
            pA[2] = tf32cvt(pa[u].z); pA[3] = tf32cvt(pa[u].w);
            unsigned* pB = &Bs[bk[u] * BSTRIDE + bnq[u] * 4];
            pB[0] = tf32cvt(pb[u].x); pB[1] = tf32cvt(pb[u].y);
            pB[2] = tf32cvt(pb[u].z); pB[3] = tf32cvt(pb[u].w);
        }
        __syncthreads();
        if (kt + 16 < DIN) {
#pragma unroll
            for (int u = 0; u < 2; u++) {
                pa[u] = *(const float4*)(x + (size_t)(m0 + arow[u]) * DIN + kt + 16 + ac4[u] * 4);
                pb[u] = *(const float4*)(W + (size_t)(kt + 16 + bk[u]) * DH + nn0 + bnq[u] * 4);
            }
        }
#pragma unroll
        for (int kk = 0; kk < 16; kk += 8) {
            unsigned a[2][4], b[8][2];
#pragma unroll
            for (int mf = 0; mf < 2; mf++) {
                int rb = wm * 32 + mf * 16 + grp;
                a[mf][0] = As[rb * ASTRIDE + kk + tg];
                a[mf][1] = As[(rb + 8) * ASTRIDE + kk + tg];
                a[mf][2] = As[rb * ASTRIDE + kk + tg + 4];
                a[mf][3] = As[(rb + 8) * ASTRIDE + kk + tg + 4];
            }
#pragma unroll
            for (int nf = 0; nf < 8; nf++) {
                int cb = wn * 64 + nf * 8 + grp;
                b[nf][0] = Bs[(kk + tg) * BSTRIDE + cb];
                b[nf][1] = Bs[(kk + tg + 4) * BSTRIDE + cb];
            }
#pragma unroll
            for (int mf = 0; mf < 2; mf++)
#pragma unroll
                for (int nf = 0; nf < 8; nf++) {
                    asm volatile(
                        "mma.sync.aligned.m16n8k8.row.col.f32.tf32.tf32.f32 "
                        "{%0,%1,%2,%3}, {%4,%5,%6,%7}, {%8,%9}, {%0,%1,%2,%3};"
                        : "+f"(c[mf][nf][0]), "+f"(c[mf][nf][1]),
                          "+f"(c[mf][nf][2]), "+f"(c[mf][nf][3])
                        : "r"(a[mf][0]), "r"(a[mf][1]), "r"(a[mf][2]), "r"(a[mf][3]),
                          "r"(b[nf][0]), "r"(b[nf][1]));
                }
        }
    }

#pragma unroll
    for (int mf = 0; mf < 2; mf++) {
        int row0 = m0 + wm * 32 + mf * 16 + grp;
#pragma unroll
        for (int nf = 0; nf < 8; nf++) {
            int h = nn0 + wn * 64 + nf * 8 + tg * 2;
            float2 bb = *(const float2*)(bias + h);
            {
                int b = row0 >> 10, t = row0 & 1023;
                float2 v = make_float2(c[mf][nf][0] + bb.x, c[mf][nf][1] + bb.y);
                *(float2*)(g_gates + ((size_t)(t * BATCH + b) * 4 + g) * DH + h) = v;
            }
            {
                int r1 = row0 + 8;
                int b = r1 >> 10, t = r1 & 1023;
                float2 v = make_float2(c[mf][nf][2] + bb.x, c[mf][nf][3] + bb.y);
                *(float2*)(g_gates + ((size_t)(t * BATCH + b) * 4 + g) * DH + h) = v;
            }
        }
    }
}

// ---------------- phase 2: persistent recurrence, tensor-core ---------------
// 128 CTAs x 512 threads (16 warps). CTA bx owns outputs n = g*4+h2 (16 cols),
// h = bx*4+h2. Warp ws covers K in [32*ws, 32*ws+32). Split-tf32 (3 mma).
// H stored PRE-SPLIT (big/small) by producers -> zero cvt in consumer loop.
// Sync: producer st.release.gpu flag; consumers ld.acquire.gpu poll (all lanes).
#define STEP_THREADS 512
#define RS 24
#define SMEM_STEPS (16 * 32 * RS * 4)

#define MMA_T(C, A, B)                                                          \
    asm volatile(                                                               \
        "mma.sync.aligned.m16n8k8.row.col.f32.tf32.tf32.f32 "                   \
        "{%0,%1,%2,%3}, {%4,%5,%6,%7}, {%8,%9}, {%0,%1,%2,%3};"                 \
        : "+f"(C[0]), "+f"(C[1]), "+f"(C[2]), "+f"(C[3])                        \
        : "r"(A[0]), "r"(A[1]), "r"(A[2]), "r"(A[3]), "r"(B[0]), "r"(B[1]));

__global__ __launch_bounds__(STEP_THREADS, 1) void k_steps(float* __restrict__ out) {
    extern __shared__ float red[];   // [ws][m(32)][RS], n in [0,16)

    int tid = threadIdx.x;
    int lane = tid & 31;
    int ws = tid >> 5;
    int grp = lane >> 2, tg = lane & 3;
    int bx = blockIdx.x;

    // ---- precompute W fragments (big + small), resident all steps ----------
    unsigned wb[2][4][2], wsm[2][4][2];
#pragma unroll
    for (int nt = 0; nt < 2; nt++) {
        int n = nt * 8 + grp;
        int g = n >> 2, h2 = n & 3;
        const float* wrow = g_Wt + (size_t)g * DH * DH + (size_t)(bx * 4 + h2) * DH;
#pragma unroll
        for (int q = 0; q < 4; q++) {
            int k0 = 32 * ws + 8 * q + tg;
#pragma unroll
            for (int u = 0; u < 2; u++) {
                float w = wrow[k0 + u * 4];
                unsigned b = tf32cvt(w);
                wb[nt][q][u] = b;
                wsm[nt][q][u] = tf32cvt(w - __uint_as_float(b));
            }
        }
    }

    // every lane polls one of this warp's 8 producer flags (CTAs 8*ws..8*ws+7)
    const unsigned* myflag = &g_flags[(ws * 8 + (lane & 7)) * 32];

    // per-thread reduction/epilogue identity: (m, n)
    int m_r = tid >> 4;
    int n_r = tid & 15;
    const float* gsrc = g_gates + ((size_t)m_r * 4 + (n_r >> 2)) * DH + bx * 4 + (n_r & 3);

    // leader (n_r < 4) H-write index in fragment layout
    int hg_e = bx * 4 + n_r;                 // n_r = h2 for leaders
    int mtE = m_r >> 4, mmE = m_r & 15;
    int grpE = mmE & 7, mhighE = mmE >> 3;
    int K8E = hg_e >> 3, kkE = hg_e & 7;
    int tgE = kkE & 3, khighE = kkE >> 2;
    int idxE = (((K8E * 2 + mtE) * 32) + grpE * 4 + tgE) * 4 + (khighE * 2 + mhighE);
    float Creg = 0.f;

    for (int t = 0; t < SEQ; t++) {
        // ---- prefetch this thread's gate pre-activation (DRAM, overlaps wait)
        float gv = __ldg(gsrc + (size_t)t * BATCH * 4 * DH);

        // ---- wait for this warp's 8 producers (skip t=0: H0 preset to 0) ----
        if (t > 0) {
            unsigned target = (unsigned)t;
            unsigned v;
            do {
                asm volatile("ld.acquire.gpu.global.u32 %0, [%1];"
                             : "=r"(v) : "l"(myflag) : "memory");
            } while (v < target);
            __syncwarp();
        }

        // ---- tensor-core compute: C[2][2][4] over K=32, pre-split H --------
        const float* Hb = g_H[t & 1][0];
        const float* Hs = g_H[t & 1][1];
        float c[2][2][4];
#pragma unroll
        for (int i = 0; i < 2; i++)
#pragma unroll
            for (int j = 0; j < 2; j++)
#pragma unroll
                for (int q = 0; q < 4; q++) c[i][j][q] = 0.f;

#pragma unroll
        for (int q = 0; q < 4; q++) {
            int K8 = ws * 4 + q;
#pragma unroll
            for (int mt = 0; mt < 2; mt++) {
                size_t off = ((size_t)(K8 * 2 + mt) * 32 + lane) * 4;
                unsigned ab[4], as_[4];
                asm("ld.global.cg.v4.b32 {%0,%1,%2,%3}, [%4];"
                    : "=r"(ab[0]), "=r"(ab[1]), "=r"(ab[2]), "=r"(ab[3])
                    : "l"(Hb + off));
                asm("ld.global.cg.v4.b32 {%0,%1,%2,%3}, [%4];"
                    : "=r"(as_[0]), "=r"(as_[1]), "=r"(as_[2]), "=r"(as_[3])
                    : "l"(Hs + off));
#pragma unroll
                for (int nt = 0; nt < 2; nt++) {
                    MMA_T(c[mt][nt], ab,  wb[nt][q]);
                    MMA_T(c[mt][nt], ab,  wsm[nt][q]);
                    MMA_T(c[mt][nt], as_, wb[nt][q]);
                }
            }
        }

        // ---- store partials to red[ws][m][n] ----
#pragma unroll
        for (int mt = 0; mt < 2; mt++)
#pragma unroll
            for (int nt = 0; nt < 2; nt++) {
                float* r0 = &red[((ws * 32) + 16 * mt + grp) * RS + nt * 8 + 2 * tg];
                *(float2*)r0            = make_float2(c[mt][nt][0], c[mt][nt][1]);
                *(float2*)(r0 + 8 * RS) = make_float2(c[mt][nt][2], c[mt][nt][3]);
            }
        __syncthreads();

        // ---- 16-way k-split reduction (all 512 threads, one (m,n) each) ----
        float s0 = gv, s1 = 0.f, s2 = 0.f, s3 = 0.f;
        {
            const float* rp = &red[m_r * RS + n_r];
#pragma unroll
            for (int w4 = 0; w4 < 4; w4++) {
                s0 += rp[(w4 * 4 + 0) * 32 * RS];
                s1 += rp[(w4 * 4 + 1) * 32 * RS];
                s2 += rp[(w4 * 4 + 2) * 32 * RS];
                s3 += rp[(w4 * 4 + 3) * 32 * RS];
            }
        }
        float s = (s0 + s1) + (s2 + s3);

        // gather the 4 gate sums to leaders (n_r < 4) via shfl
        float v1 = __shfl_sync(0xffffffffu, s, lane + 4);
        float v2 = __shfl_sync(0xffffffffu, s, lane + 8);
        float v3 = __shfl_sync(0xffffffffu, s, lane + 12);

        float Hn = 0.f;
        if (n_r < 4) {
            float I  = 1.f / (1.f + __expf(-s));
            float F  = 1.f / (1.f + __expf(-v1));
            float O  = 1.f / (1.f + __expf(-v2));
            float e2 = __expf(2.f * v3);
            float Cc = 1.f - 2.f / (e2 + 1.f);     // tanh

            Creg = F * Creg + I * Cc;
            float ec = __expf(2.f * Creg);
            Hn = O * (1.f - 2.f / (ec + 1.f));

            // pre-split store for next step's consumers
            unsigned hb = tf32cvt(Hn);
            float hbf = __uint_as_float(hb);
            float hsf = __uint_as_float(tf32cvt(Hn - hbf));
            int p = (t + 1) & 1;
            __stcg(&g_H[p][0][idxE], hbf);
            __stcg(&g_H[p][1][idxE], hsf);
        }
        __syncthreads();

        // ---- publish: release store of this CTA's flag ----
        if (tid == 0) {
            asm volatile("st.release.gpu.global.u32 [%0], %1;"
                         :: "l"(&g_flags[bx * 32]), "r"((unsigned)(t + 1)) : "memory");
        }
        if (n_r < 4)
            out[((size_t)m_r * SEQ + t) * DH + hg_e] = Hn;
    }
}

// ---------------- final H copy ---------------------------------------------
__global__ void k_final(float* __restrict__ out) {
    int i = blockIdx.x * blockDim.x + threadIdx.x;
    if (i < BATCH * DH) {
        int m = i >> 9, h = i & 511;
        int mt = m >> 4, mm = m & 15;
        int grp = mm & 7, mhigh = mm >> 3;
        int K8 = h >> 3, kk = h & 7;
        int tg = kk & 3, khigh = kk >> 2;
        int idx = (((K8 * 2 + mt) * 32) + grp * 4 + tg) * 4 + (khigh * 2 + mhigh);
        out[(size_t)BATCH * SEQ * DH + i] = g_H[0][0][idx] + g_H[0][1][idx];
    }
}

// ---------------- launch ----------------------------------------------------
extern "C" void kernel_launch(void* const* d_in, const int* in_sizes, int n_in,
                              void* d_out, int out_size) {
    const float* x   = (const float*)d_in[0];
    const float* Wxi = (const float*)d_in[1];
    const float* Whi = (const float*)d_in[2];
    const float* bi  = (const float*)d_in[3];
    const float* Wxf = (const float*)d_in[4];
    const float* Whf = (const float*)d_in[5];
    const float* bf  = (const float*)d_in[6];
    const float* Wxo = (const float*)d_in[7];
    const float* Who = (const float*)d_in[8];
    const float* bo  = (const float*)d_in[9];
    const float* Wxc = (const float*)d_in[10];
    const float* Whc = (const float*)d_in[11];
    const float* bc  = (const float*)d_in[12];
    float* out = (float*)d_out;

    static int smem_set = 0;
    if (!smem_set) {
        cudaFuncSetAttribute(k_steps, cudaFuncAttributeMaxDynamicSharedMemorySize, SMEM_STEPS);
        smem_set = 1;
    }

    k_init<<<256, 256>>>();
    k_transpose<<<dim3(16, 16, 4), dim3(32, 8)>>>(Whi, Whf, Who, Whc);
    k_xproj<<<dim3(2048 / 128, 32768 / 128), 256>>>(x, Wxi, Wxf, Wxo, Wxc, bi, bf, bo, bc);
    k_steps<<<NCTA, STEP_THREADS, SMEM_STEPS>>>(out);
    k_final<<<64, 256>>>(out);
}